// round 11
// baseline (speedup 1.0000x reference)
#include <cuda_runtime.h>
#include <cuda_fp16.h>
#include <cstdint>

#define BB 2
#define LL 2048
#define DM 1024
#define NH 16
#define DK 64
#define MROWS (BB * LL)   // 4096

typedef __half hf;

// ---------------------------------------------------------------------------
// Global scratch (no allocations allowed)
// ---------------------------------------------------------------------------
__device__ hf g_xhi[3][MROWS * DM];             // split inputs q,k,v (v: hi only)
__device__ hf g_xlo[3][MROWS * DM];
__device__ hf g_wthi[3 * NH * DK * DM];         // W transposed [z][h][n][k]
__device__ hf g_wtlo[3 * NH * DK * DM];
__device__ hf g_wphi[DM * DM];                  // w_proj [n][k]
__device__ hf g_wplo[DM * DM];

__device__ hf g_qhi[NH * BB * LL * DK];         // [hb][l][k]
__device__ hf g_qlo[NH * BB * LL * DK];
__device__ hf g_khi[NH * BB * LL * DK];
__device__ hf g_klo[NH * BB * LL * DK];
__device__ hf g_vthi[NH * BB * DK * LL];        // [hb][d][l]  (V transposed, hi only)

__device__ hf g_atthi[MROWS * DM];              // attention output (hi only)

// ---------------------------------------------------------------------------
// PTX helpers (base-ISA: mma.sync / ldmatrix / cp.async)
// ---------------------------------------------------------------------------
__device__ __forceinline__ uint32_t smem_u32(const void* p) {
    uint32_t a;
    asm("{ .reg .u64 t; cvta.to.shared.u64 t, %1; cvt.u32.u64 %0, t; }"
        : "=r"(a) : "l"(p));
    return a;
}
__device__ __forceinline__ void ldm4(uint32_t r[4], uint32_t a) {
    asm volatile("ldmatrix.sync.aligned.m8n8.x4.shared.b16 {%0,%1,%2,%3}, [%4];"
        : "=r"(r[0]), "=r"(r[1]), "=r"(r[2]), "=r"(r[3]) : "r"(a));
}
__device__ __forceinline__ void mma16816(float c[4], const uint32_t a[4],
                                         const uint32_t b[2]) {
    asm volatile("mma.sync.aligned.m16n8k16.row.col.f32.f16.f16.f32 "
        "{%0,%1,%2,%3}, {%4,%5,%6,%7}, {%8,%9}, {%0,%1,%2,%3};"
        : "+f"(c[0]), "+f"(c[1]), "+f"(c[2]), "+f"(c[3])
        : "r"(a[0]), "r"(a[1]), "r"(a[2]), "r"(a[3]), "r"(b[0]), "r"(b[1]));
}
#define CP16(dst, src) \
    asm volatile("cp.async.cg.shared.global [%0], [%1], 16;" \
                 :: "r"(dst), "l"(src) : "memory")
#define CP_COMMIT() asm volatile("cp.async.commit_group;" ::: "memory")
#define CP_WAIT2()  asm volatile("cp.async.wait_group 2;" ::: "memory")
#define CP_WAIT1()  asm volatile("cp.async.wait_group 1;" ::: "memory")
#define CP_WAIT0()  asm volatile("cp.async.wait_group 0;" ::: "memory")

// 128B-row tile swizzle: unit = 16B column, XOR by row&7 (conflict-free ldmatrix)
__device__ __forceinline__ uint32_t swz(int row, int u) {
    return (uint32_t)(row * 128 + ((u ^ (row & 7)) << 4));
}
// pack two fp32 into f16x2 (first arg -> low half)
__device__ __forceinline__ uint32_t pack_hf(float lo, float hi) {
    uint32_t r;
    asm("cvt.rn.f16x2.f32 %0, %1, %2;" : "=r"(r) : "f"(hi), "f"(lo));
    return r;
}

// ---------------------------------------------------------------------------
// Conversion kernels (unchanged)
// ---------------------------------------------------------------------------
__global__ void conv_split_kernel(const float* __restrict__ q,
                                  const float* __restrict__ k,
                                  const float* __restrict__ v,
                                  const float* __restrict__ wp)
{
    const int sel = blockIdx.y;
    const float* src;
    hf *hi, *lo;
    bool wlo = true;
    int n4;
    if      (sel == 0) { src = q;  hi = g_xhi[0]; lo = g_xlo[0]; n4 = MROWS * DM / 4; }
    else if (sel == 1) { src = k;  hi = g_xhi[1]; lo = g_xlo[1]; n4 = MROWS * DM / 4; }
    else if (sel == 2) { src = v;  hi = g_xhi[2]; lo = nullptr;  n4 = MROWS * DM / 4; wlo = false; }
    else               { src = wp; hi = g_wphi;   lo = g_wplo;   n4 = DM * DM / 4; }

    int i = blockIdx.x * 256 + threadIdx.x;
    if (i >= n4) return;
    float4 vv = ((const float4*)src)[i];
    uint32_t h01 = pack_hf(vv.x, vv.y);
    uint32_t h23 = pack_hf(vv.z, vv.w);
    ((uint32_t*)hi)[2 * i]     = h01;
    ((uint32_t*)hi)[2 * i + 1] = h23;
    if (wlo) {
        __half2 f01 = *(__half2*)&h01, f23 = *(__half2*)&h23;
        ((uint32_t*)lo)[2 * i] =
            pack_hf(vv.x - __half2float(f01.x), vv.y - __half2float(f01.y));
        ((uint32_t*)lo)[2 * i + 1] =
            pack_hf(vv.z - __half2float(f23.x), vv.w - __half2float(f23.y));
    }
}

__global__ void conv_wt_kernel(const float* __restrict__ wq,
                               const float* __restrict__ wk,
                               const float* __restrict__ wv)
{
    __shared__ float ts[64][65];
    const int h = blockIdx.x, z = blockIdx.y;
    const float* W = (z == 0 ? wq : z == 1 ? wk : wv) + (size_t)h * DM * DK;
    hf* hi = g_wthi + (size_t)(z * NH + h) * DK * DM;
    hf* lo = g_wtlo + (size_t)(z * NH + h) * DK * DM;
    const int t = threadIdx.x;
    for (int k0 = 0; k0 < DM; k0 += 64) {
        __syncthreads();
        for (int i = 0; i < 16; ++i) {
            int idx = i * 256 + t;
            int r = idx >> 6, c = idx & 63;
            ts[r][c] = W[(size_t)(k0 + r) * DK + c];
        }
        __syncthreads();
        for (int i = 0; i < 16; ++i) {
            int idx = i * 256 + t;
            int n = idx >> 6, c = idx & 63;
            float x = ts[c][n];
            hf h0 = __float2half_rn(x);
            hi[(size_t)n * DM + k0 + c] = h0;
            lo[(size_t)n * DM + k0 + c] = __float2half_rn(x - __half2float(h0));
        }
    }
}

// ---------------------------------------------------------------------------
// GEMM core (R7 config — best measured): single 64KB stage, 2 CTAs/SM;
// co-resident CTA hides fill latency. USE_ALO: 3-MMA split; else 2-MMA.
// ---------------------------------------------------------------------------
#define GEMM_SMEM (65536 + 128)

template <bool USE_ALO>
__device__ __forceinline__ void gemm_fill(uint32_t base,
    const hf* __restrict__ Ahi, const hf* __restrict__ Alo, size_t ar0,
    const hf* __restrict__ Bhi, const hf* __restrict__ Blo, size_t br0,
    int k0)
{
    const int t = threadIdx.x;
    #pragma unroll
    for (int i = 0; i < 4; ++i) {
        int g = i * 256 + t;
        int row = g >> 3, u = g & 7;
        size_t goff = (size_t)row * DM + k0 + u * 8;
        uint32_t s = swz(row, u);
        CP16(base + s, Ahi + (size_t)ar0 * DM + goff);
        if (USE_ALO) CP16(base + 16384 + s, Alo + (size_t)ar0 * DM + goff);
        CP16(base + 32768 + s, Bhi + (size_t)br0 * DM + goff);
        CP16(base + 49152 + s, Blo + (size_t)br0 * DM + goff);
    }
}

template <bool USE_ALO>
__device__ __forceinline__ void gemm_core(uint32_t sb,
    const hf* Ahi, const hf* Alo, size_t ar0,
    const hf* Bhi, const hf* Blo, size_t br0,
    float C[4][4][4])
{
    const int t = threadIdx.x, w = t >> 5, l = t & 31;
    const int wm = (w & 1) * 64, wn = (w >> 1) * 32;
    const int mi = l >> 3;

    gemm_fill<USE_ALO>(sb, Ahi, Alo, ar0, Bhi, Blo, br0, 0);
    CP_COMMIT();

    for (int c = 0; c < 16; ++c) {
        CP_WAIT0();
        __syncthreads();

        #pragma unroll
        for (int kt = 0; kt < 4; ++kt) {
            uint32_t ahi[4][4], alo[4][4];
            #pragma unroll
            for (int i = 0; i < 4; ++i) {
                int row = wm + 16 * i + (l & 7) + ((mi & 1) << 3);
                int u = kt * 2 + (mi >> 1);
                ldm4(ahi[i], sb + swz(row, u));
                if (USE_ALO) ldm4(alo[i], sb + 16384 + swz(row, u));
            }
            uint32_t bhi[4][2], blo[4][2];
            #pragma unroll
            for (int jp = 0; jp < 2; ++jp) {
                int row = wn + jp * 16 + ((mi >> 1) << 3) + (l & 7);
                int u = kt * 2 + (mi & 1);
                uint32_t r4[4];
                ldm4(r4, sb + 32768 + swz(row, u));
                bhi[2*jp][0] = r4[0]; bhi[2*jp][1] = r4[1];
                bhi[2*jp+1][0] = r4[2]; bhi[2*jp+1][1] = r4[3];
                ldm4(r4, sb + 49152 + swz(row, u));
                blo[2*jp][0] = r4[0]; blo[2*jp][1] = r4[1];
                blo[2*jp+1][0] = r4[2]; blo[2*jp+1][1] = r4[3];
            }
            #pragma unroll
            for (int i = 0; i < 4; ++i)
                #pragma unroll
                for (int j = 0; j < 4; ++j) {
                    mma16816(C[i][j], ahi[i], bhi[j]);
                    mma16816(C[i][j], ahi[i], blo[j]);
                    if (USE_ALO) mma16816(C[i][j], alo[i], bhi[j]);
                }
        }
        __syncthreads();
        if (c + 1 < 16) {
            gemm_fill<USE_ALO>(sb, Ahi, Alo, ar0, Bhi, Blo, br0, (c + 1) * 64);
            CP_COMMIT();
        }
    }
}

// ---------------------------------------------------------------------------
// Kernel: per-head-pair input projections. grid (32, 8, 3), 2 CTAs/SM.
// ---------------------------------------------------------------------------
__global__ __launch_bounds__(256, 2) void gemm_proj_mma()
{
    extern __shared__ char smraw[];
    uint32_t sb = (smem_u32(smraw) + 127) & ~127u;
    const int z = blockIdx.z, hp = blockIdx.y;
    const size_t row0 = (size_t)blockIdx.x * 128;

    float C[4][4][4] = {};
    const hf* Bhi = g_wthi + (size_t)(z * NH + 2 * hp) * DK * DM;
    const hf* Blo = g_wtlo + (size_t)(z * NH + 2 * hp) * DK * DM;
    if (z < 2)
        gemm_core<true >(sb, g_xhi[z], g_xlo[z], row0, Bhi, Blo, 0, C);
    else
        gemm_core<false>(sb, g_xhi[z], nullptr,  row0, Bhi, Blo, 0, C);

    const int t = threadIdx.x, w = t >> 5, l = t & 31;
    const int gid = l >> 2, tig = l & 3;
    const int wm = (w & 1) * 64, wn = (w >> 1) * 32;

    #pragma unroll
    for (int i = 0; i < 4; ++i)
        #pragma unroll
        for (int j = 0; j < 4; ++j) {
            const int col = wn + 8 * j + 2 * tig;
            const int head = 2 * hp + (col >> 6), d = col & 63;
            const size_t r0 = row0 + wm + 16 * i + gid, r1 = r0 + 8;
            const size_t b = r0 >> 11;
            const size_t hb = (size_t)head * BB + b;
            if (z == 2) {
                const size_t lq0 = r0 & 2047, lq1 = r1 & 2047;
                hf* V = g_vthi + hb * (size_t)DK * LL;
                V[(size_t)d * LL + lq0]       = __float2half_rn(C[i][j][0]);
                V[(size_t)(d + 1) * LL + lq0] = __float2half_rn(C[i][j][1]);
                V[(size_t)d * LL + lq1]       = __float2half_rn(C[i][j][2]);
                V[(size_t)(d + 1) * LL + lq1] = __float2half_rn(C[i][j][3]);
            } else {
                hf* Hi = (z == 0 ? g_qhi : g_khi);
                hf* Lo = (z == 0 ? g_qlo : g_klo);
                #pragma unroll
                for (int rr = 0; rr < 2; ++rr) {
                    const size_t r = rr ? r1 : r0;
                    const float f0 = C[i][j][2 * rr], f1 = C[i][j][2 * rr + 1];
                    uint32_t hh = pack_hf(f0, f1);
                    __half2 h2 = *(__half2*)&hh;
                    uint32_t ll = pack_hf(f0 - __half2float(h2.x),
                                          f1 - __half2float(h2.y));
                    const size_t o = (hb * LL + (r & 2047)) * DK + d;
                    *(uint32_t*)(Hi + o) = hh;
                    *(uint32_t*)(Lo + o) = ll;
                }
            }
        }
}

// ---------------------------------------------------------------------------
// Kernel: output projection + bias. grid (32, 8). 2-MMA, 2 CTAs/SM.
// ---------------------------------------------------------------------------
__global__ __launch_bounds__(256, 2) void gemm_out_mma(
    const float* __restrict__ bias, float* __restrict__ out)
{
    extern __shared__ char smraw[];
    uint32_t sb = (smem_u32(smraw) + 127) & ~127u;
    const size_t row0 = (size_t)blockIdx.x * 128;
    const size_t col0 = (size_t)blockIdx.y * 128;

    float C[4][4][4] = {};
    gemm_core<false>(sb, g_atthi, nullptr, row0, g_wphi, g_wplo, col0, C);

    const int t = threadIdx.x, w = t >> 5, l = t & 31;
    const int gid = l >> 2, tig = l & 3;
    const int wm = (w & 1) * 64, wn = (w >> 1) * 32;

    #pragma unroll
    for (int i = 0; i < 4; ++i)
        #pragma unroll
        for (int j = 0; j < 4; ++j) {
            size_t col = col0 + wn + 8 * j + 2 * tig;
            size_t r = row0 + wm + 16 * i + gid;
            float2 b2 = *(const float2*)(bias + col);
            *(float2*)(out + r * DM + col) =
                make_float2(C[i][j][0] + b2.x, C[i][j][1] + b2.y);
            *(float2*)(out + (r + 8) * DM + col) =
                make_float2(C[i][j][2] + b2.x, C[i][j][3] + b2.y);
        }
}

// ---------------------------------------------------------------------------
// Flash attention on HMMA (fp16). grid (16, 32). 128 q-rows/CTA, 64-key tiles.
// QK: 3-MMA split. PV: 1-MMA. Row sums via ones-MMA (osum accumulator) —
// removes sum FADDs + shuffles from the softmax critical path.
// 4-stage ring + fill-ahead-2, one barrier/iter. 2 CTAs/SM.
// ---------------------------------------------------------------------------
#define ATTN_STAGE 24576
#define ATTN_SMEM (16384 + 4 * ATTN_STAGE + 128)

__device__ __forceinline__ void attn_fill(uint32_t base,
    const hf* khi, const hf* klo, const hf* vthi, int j0)
{
    const int t = threadIdx.x;
    #pragma unroll
    for (int i = 0; i < 2; ++i) {
        int g = i * 256 + t;
        int row = g >> 3, u = g & 7;
        uint32_t s = swz(row, u);
        CP16(base + s,         khi  + (size_t)(j0 + row) * DK + u * 8);
        CP16(base + 8192 + s,  klo  + (size_t)(j0 + row) * DK + u * 8);
        CP16(base + 16384 + s, vthi + (size_t)row * LL + j0 + u * 8);
    }
}

__global__ __launch_bounds__(256, 2) void attn_mma()
{
    extern __shared__ char smraw[];
    const uint32_t sb = (smem_u32(smraw) + 127) & ~127u;
    const uint32_t QLO = sb, ST0 = sb + 16384;

    const int hb = blockIdx.y;
    const int h = hb >> 1, b = hb & 1;
    const int l0 = blockIdx.x * 128;
    const hf* qhi = g_qhi + (size_t)hb * LL * DK;
    const hf* qlo = g_qlo + (size_t)hb * LL * DK;
    const hf* khi = g_khi + (size_t)hb * LL * DK;
    const hf* klo = g_klo + (size_t)hb * LL * DK;
    const hf* vthi = g_vthi + (size_t)hb * DK * LL;

    const int t = threadIdx.x, w = t >> 5, l = t & 31;
    const int gid = l >> 2, tig = l & 3;
    const int mi = l >> 3;

    // Init: Q-hi staged temporarily in stage0 region; Q-lo resident at QLO.
    #pragma unroll
    for (int i = 0; i < 4; ++i) {
        int g = i * 256 + t;
        int row = g >> 3, u = g & 7;
        uint32_t s = swz(row, u);
        *(uint4*)(smraw + (ST0 - sb) + s) =
            *(const uint4*)(qhi + (size_t)(l0 + row) * DK + u * 8);
        *(uint4*)(smraw + (QLO - sb) + s) =
            *(const uint4*)(qlo + (size_t)(l0 + row) * DK + u * 8);
    }
    __syncthreads();

    uint32_t qfh[4][4];
    #pragma unroll
    for (int kt = 0; kt < 4; ++kt) {
        int row = w * 16 + (l & 7) + ((mi & 1) << 3);
        int u = kt * 2 + (mi >> 1);
        ldm4(qfh[kt], ST0 + swz(row, u));
    }
    __syncthreads();

    attn_fill(ST0, khi, klo, vthi, 0);
    CP_COMMIT();
    attn_fill(ST0 + ATTN_STAGE, khi, klo, vthi, 64);
    CP_COMMIT();

    const uint32_t ones2[2] = { 0x3C003C00u, 0x3C003C00u };   // fp16 1.0 x4

    float o[8][4] = {};
    float osum[4] = {};            // row sums via ones-MMA (cols all equal)
    float m0 = -1e30f, m1 = -1e30f;

    for (int jt = 0; jt < 32; ++jt) {
        if (jt + 2 < 32) {
            attn_fill(ST0 + ((jt + 2) & 3) * ATTN_STAGE, khi, klo, vthi,
                      (jt + 2) * 64);
            CP_COMMIT();
            CP_WAIT2();
        } else if (jt + 1 < 32) {
            CP_WAIT1();
        } else {
            CP_WAIT0();
        }
        __syncthreads();
        const uint32_t tb = ST0 + (jt & 3) * ATTN_STAGE;

        // ---- S = Q K^T (3-MMA split) ----
        float s[8][4] = {};
        #pragma unroll
        for (int kt = 0; kt < 4; ++kt) {
            uint32_t qfl[4];
            {
                int row = w * 16 + (l & 7) + ((mi & 1) << 3);
                int u = kt * 2 + (mi >> 1);
                ldm4(qfl, QLO + swz(row, u));
            }
            uint32_t kh[8][2], kl[8][2];
            #pragma unroll
            for (int jp = 0; jp < 4; ++jp) {
                int row = jp * 16 + ((mi >> 1) << 3) + (l & 7);
                int u = kt * 2 + (mi & 1);
                uint32_t r4[4];
                ldm4(r4, tb + swz(row, u));
                kh[2*jp][0] = r4[0]; kh[2*jp][1] = r4[1];
                kh[2*jp+1][0] = r4[2]; kh[2*jp+1][1] = r4[3];
                ldm4(r4, tb + 8192 + swz(row, u));
                kl[2*jp][0] = r4[0]; kl[2*jp][1] = r4[1];
                kl[2*jp+1][0] = r4[2]; kl[2*jp+1][1] = r4[3];
            }
            #pragma unroll
            for (int n = 0; n < 8; ++n) {
                mma16816(s[n], qfh[kt], kh[n]);
                mma16816(s[n], qfh[kt], kl[n]);
                mma16816(s[n], qfl,     kh[n]);
            }
        }

        // ---- online softmax: max-reduce + exp only (sum via ones-MMA) ----
        float rm0 = -1e30f, rm1 = -1e30f;
        #pragma unroll
        for (int n = 0; n < 8; ++n) {
            rm0 = fmaxf(rm0, fmaxf(s[n][0], s[n][1]));
            rm1 = fmaxf(rm1, fmaxf(s[n][2], s[n][3]));
        }
        rm0 = fmaxf(rm0, __shfl_xor_sync(0xffffffffu, rm0, 1));
        rm0 = fmaxf(rm0, __shfl_xor_sync(0xffffffffu, rm0, 2));
        rm1 = fmaxf(rm1, __shfl_xor_sync(0xffffffffu, rm1, 1));
        rm1 = fmaxf(rm1, __shfl_xor_sync(0xffffffffu, rm1, 2));
        const float mn0 = fmaxf(m0, rm0), mn1 = fmaxf(m1, rm1);
        const float sc0 = __expf(m0 - mn0), sc1 = __expf(m1 - mn1);
        m0 = mn0; m1 = mn1;
        #pragma unroll
        for (int n = 0; n < 8; ++n) {
            s[n][0] = __expf(s[n][0] - mn0); s[n][1] = __expf(s[n][1] - mn0);
            s[n][2] = __expf(s[n][2] - mn1); s[n][3] = __expf(s[n][3] - mn1);
        }
        #pragma unroll
        for (int n = 0; n < 8; ++n) {
            o[n][0] *= sc0; o[n][1] *= sc0;
            o[n][2] *= sc1; o[n][3] *= sc1;
        }
        osum[0] *= sc0; osum[1] *= sc0;
        osum[2] *= sc1; osum[3] *= sc1;

        // ---- P (hi) x V (hi) + ones-MMA row sums ----
        #pragma unroll
        for (int kt = 0; kt < 4; ++kt) {
            uint32_t pah[4] = {
                pack_hf(s[2*kt][0],   s[2*kt][1]),
                pack_hf(s[2*kt][2],   s[2*kt][3]),
                pack_hf(s[2*kt+1][0], s[2*kt+1][1]),
                pack_hf(s[2*kt+1][2], s[2*kt+1][3]) };
            mma16816(osum, pah, ones2);
            uint32_t vh[8][2];
            #pragma unroll
            for (int jp = 0; jp < 4; ++jp) {
                int row = jp * 16 + ((mi >> 1) << 3) + (l & 7);
                int u = kt * 2 + (mi & 1);
                uint32_t r4[4];
                ldm4(r4, tb + 16384 + swz(row, u));
                vh[2*jp][0] = r4[0]; vh[2*jp][1] = r4[1];
                vh[2*jp+1][0] = r4[2]; vh[2*jp+1][1] = r4[3];
            }
            #pragma unroll
            for (int n = 0; n < 8; ++n)
                mma16816(o[n], pah, vh[n]);
        }
    }

    // ---- epilogue: (o / l) * q -> fp16 hi ; l = osum (cols identical) ----
    const float inv0 = 1.0f / osum[0], inv1 = 1.0f / osum[2];
    const size_t r0 = l0 + w * 16 + gid, r1 = r0 + 8;
    #pragma unroll
    for (int n = 0; n < 8; ++n) {
        const int d = 8 * n + 2 * tig;
        __half2 qh2a = *(const __half2*)(qhi + r0 * DK + d);
        __half2 ql2a = *(const __half2*)(qlo + r0 * DK + d);
        __half2 qh2b = *(const __half2*)(qhi + r1 * DK + d);
        __half2 ql2b = *(const __half2*)(qlo + r1 * DK + d);
        float qa0 = __half2float(qh2a.x) + __half2float(ql2a.x);
        float qa1 = __half2float(qh2a.y) + __half2float(ql2a.y);
        float qb0 = __half2float(qh2b.x) + __half2float(ql2b.x);
        float qb1 = __half2float(qh2b.y) + __half2float(ql2b.y);
        float v00 = o[n][0] * inv0 * qa0, v01 = o[n][1] * inv0 * qa1;
        float v10 = o[n][2] * inv1 * qb0, v11 = o[n][3] * inv1 * qb1;

        size_t o0 = ((size_t)b * LL + r0) * DM + h * DK + d;
        size_t o1 = ((size_t)b * LL + r1) * DM + h * DK + d;
        *(uint32_t*)(g_atthi + o0) = pack_hf(v00, v01);
        *(uint32_t*)(g_atthi + o1) = pack_hf(v10, v11);
    }
}

// ---------------------------------------------------------------------------
extern "C" void kernel_launch(void* const* d_in, const int* in_sizes, int n_in,
                              void* d_out, int out_size)
{
    const float* q  = (const float*)d_in[0];
    const float* k  = (const float*)d_in[1];
    const float* v  = (const float*)d_in[2];
    const float* wq = (const float*)d_in[3];
    const float* wk = (const float*)d_in[4];
    const float* wv = (const float*)d_in[5];
    const float* wp = (const float*)d_in[6];
    const float* bp = (const float*)d_in[7];
    float* out = (float*)d_out;

    cudaFuncSetAttribute(gemm_proj_mma,
                         cudaFuncAttributeMaxDynamicSharedMemorySize, GEMM_SMEM);
    cudaFuncSetAttribute(gemm_out_mma,
                         cudaFuncAttributeMaxDynamicSharedMemorySize, GEMM_SMEM);
    cudaFuncSetAttribute(attn_mma,
                         cudaFuncAttributeMaxDynamicSharedMemorySize, ATTN_SMEM);

    const int n4x = MROWS * DM / 4;
    conv_split_kernel<<<dim3((n4x + 255) / 256, 4), 256>>>(q, k, v, wp);
    conv_wt_kernel<<<dim3(NH, 3), 256>>>(wq, wk, wv);

    gemm_proj_mma<<<dim3(MROWS / 128, NH / 2, 3), 256, GEMM_SMEM>>>();

    attn_mma<<<dim3(LL / 128, NH * BB), 256, ATTN_SMEM>>>();

    gemm_out_mma<<<dim3(MROWS / 128, DM / 128), 256, GEMM_SMEM>>>(bp, out);
}

// round 12
// speedup vs baseline: 1.0021x; 1.0021x over previous
#include <cuda_runtime.h>
#include <cuda_fp16.h>
#include <cstdint>

#define BB 2
#define LL 2048
#define DM 1024
#define NH 16
#define DK 64
#define MROWS (BB * LL)   // 4096

typedef __half hf;

// ---------------------------------------------------------------------------
// Global scratch (no allocations allowed)
// ---------------------------------------------------------------------------
__device__ hf g_xhi[3][MROWS * DM];             // split inputs q,k,v (v: hi only)
__device__ hf g_xlo[3][MROWS * DM];
__device__ hf g_wthi[3 * NH * DK * DM];         // W transposed [z][h][n][k]
__device__ hf g_wtlo[3 * NH * DK * DM];
__device__ hf g_wphi[DM * DM];                  // w_proj [n][k]
__device__ hf g_wplo[DM * DM];

__device__ hf g_qhi[NH * BB * LL * DK];         // [hb][l][k]
__device__ hf g_qlo[NH * BB * LL * DK];
__device__ hf g_khi[NH * BB * LL * DK];
__device__ hf g_klo[NH * BB * LL * DK];
__device__ hf g_vthi[NH * BB * DK * LL];        // [hb][d][l]  (V transposed, hi only)

__device__ hf g_atthi[MROWS * DM];              // attention output (hi only)

// ---------------------------------------------------------------------------
// PTX helpers (base-ISA: mma.sync / ldmatrix / cp.async)
// ---------------------------------------------------------------------------
__device__ __forceinline__ uint32_t smem_u32(const void* p) {
    uint32_t a;
    asm("{ .reg .u64 t; cvta.to.shared.u64 t, %1; cvt.u32.u64 %0, t; }"
        : "=r"(a) : "l"(p));
    return a;
}
__device__ __forceinline__ void ldm4(uint32_t r[4], uint32_t a) {
    asm volatile("ldmatrix.sync.aligned.m8n8.x4.shared.b16 {%0,%1,%2,%3}, [%4];"
        : "=r"(r[0]), "=r"(r[1]), "=r"(r[2]), "=r"(r[3]) : "r"(a));
}
__device__ __forceinline__ void mma16816(float c[4], const uint32_t a[4],
                                         const uint32_t b[2]) {
    asm volatile("mma.sync.aligned.m16n8k16.row.col.f32.f16.f16.f32 "
        "{%0,%1,%2,%3}, {%4,%5,%6,%7}, {%8,%9}, {%0,%1,%2,%3};"
        : "+f"(c[0]), "+f"(c[1]), "+f"(c[2]), "+f"(c[3])
        : "r"(a[0]), "r"(a[1]), "r"(a[2]), "r"(a[3]), "r"(b[0]), "r"(b[1]));
}
#define CP16(dst, src) \
    asm volatile("cp.async.cg.shared.global [%0], [%1], 16;" \
                 :: "r"(dst), "l"(src) : "memory")
#define CP_COMMIT() asm volatile("cp.async.commit_group;" ::: "memory")
#define CP_WAIT2()  asm volatile("cp.async.wait_group 2;" ::: "memory")
#define CP_WAIT1()  asm volatile("cp.async.wait_group 1;" ::: "memory")
#define CP_WAIT0()  asm volatile("cp.async.wait_group 0;" ::: "memory")

// 128B-row tile swizzle: unit = 16B column, XOR by row&7 (conflict-free ldmatrix)
__device__ __forceinline__ uint32_t swz(int row, int u) {
    return (uint32_t)(row * 128 + ((u ^ (row & 7)) << 4));
}
// pack two fp32 into f16x2 (first arg -> low half)
__device__ __forceinline__ uint32_t pack_hf(float lo, float hi) {
    uint32_t r;
    asm("cvt.rn.f16x2.f32 %0, %1, %2;" : "=r"(r) : "f"(hi), "f"(lo));
    return r;
}

// ---------------------------------------------------------------------------
// Conversion kernels (unchanged)
// ---------------------------------------------------------------------------
__global__ void conv_split_kernel(const float* __restrict__ q,
                                  const float* __restrict__ k,
                                  const float* __restrict__ v,
                                  const float* __restrict__ wp)
{
    const int sel = blockIdx.y;
    const float* src;
    hf *hi, *lo;
    bool wlo = true;
    int n4;
    if      (sel == 0) { src = q;  hi = g_xhi[0]; lo = g_xlo[0]; n4 = MROWS * DM / 4; }
    else if (sel == 1) { src = k;  hi = g_xhi[1]; lo = g_xlo[1]; n4 = MROWS * DM / 4; }
    else if (sel == 2) { src = v;  hi = g_xhi[2]; lo = nullptr;  n4 = MROWS * DM / 4; wlo = false; }
    else               { src = wp; hi = g_wphi;   lo = g_wplo;   n4 = DM * DM / 4; }

    int i = blockIdx.x * 256 + threadIdx.x;
    if (i >= n4) return;
    float4 vv = ((const float4*)src)[i];
    uint32_t h01 = pack_hf(vv.x, vv.y);
    uint32_t h23 = pack_hf(vv.z, vv.w);
    ((uint32_t*)hi)[2 * i]     = h01;
    ((uint32_t*)hi)[2 * i + 1] = h23;
    if (wlo) {
        __half2 f01 = *(__half2*)&h01, f23 = *(__half2*)&h23;
        ((uint32_t*)lo)[2 * i] =
            pack_hf(vv.x - __half2float(f01.x), vv.y - __half2float(f01.y));
        ((uint32_t*)lo)[2 * i + 1] =
            pack_hf(vv.z - __half2float(f23.x), vv.w - __half2float(f23.y));
    }
}

__global__ void conv_wt_kernel(const float* __restrict__ wq,
                               const float* __restrict__ wk,
                               const float* __restrict__ wv)
{
    __shared__ float ts[64][65];
    const int h = blockIdx.x, z = blockIdx.y;
    const float* W = (z == 0 ? wq : z == 1 ? wk : wv) + (size_t)h * DM * DK;
    hf* hi = g_wthi + (size_t)(z * NH + h) * DK * DM;
    hf* lo = g_wtlo + (size_t)(z * NH + h) * DK * DM;
    const int t = threadIdx.x;
    for (int k0 = 0; k0 < DM; k0 += 64) {
        __syncthreads();
        for (int i = 0; i < 16; ++i) {
            int idx = i * 256 + t;
            int r = idx >> 6, c = idx & 63;
            ts[r][c] = W[(size_t)(k0 + r) * DK + c];
        }
        __syncthreads();
        for (int i = 0; i < 16; ++i) {
            int idx = i * 256 + t;
            int n = idx >> 6, c = idx & 63;
            float x = ts[c][n];
            hf h0 = __float2half_rn(x);
            hi[(size_t)n * DM + k0 + c] = h0;
            lo[(size_t)n * DM + k0 + c] = __float2half_rn(x - __half2float(h0));
        }
    }
}

// ---------------------------------------------------------------------------
// GEMM core (R7 config — best measured): single 64KB stage, 2 CTAs/SM;
// co-resident CTA hides fill latency. USE_ALO: 3-MMA split; else 2-MMA.
// ---------------------------------------------------------------------------
#define GEMM_SMEM (65536 + 128)

template <bool USE_ALO>
__device__ __forceinline__ void gemm_fill(uint32_t base,
    const hf* __restrict__ Ahi, const hf* __restrict__ Alo, size_t ar0,
    const hf* __restrict__ Bhi, const hf* __restrict__ Blo, size_t br0,
    int k0)
{
    const int t = threadIdx.x;
    #pragma unroll
    for (int i = 0; i < 4; ++i) {
        int g = i * 256 + t;
        int row = g >> 3, u = g & 7;
        size_t goff = (size_t)row * DM + k0 + u * 8;
        uint32_t s = swz(row, u);
        CP16(base + s, Ahi + (size_t)ar0 * DM + goff);
        if (USE_ALO) CP16(base + 16384 + s, Alo + (size_t)ar0 * DM + goff);
        CP16(base + 32768 + s, Bhi + (size_t)br0 * DM + goff);
        CP16(base + 49152 + s, Blo + (size_t)br0 * DM + goff);
    }
}

template <bool USE_ALO>
__device__ __forceinline__ void gemm_core(uint32_t sb,
    const hf* Ahi, const hf* Alo, size_t ar0,
    const hf* Bhi, const hf* Blo, size_t br0,
    float C[4][4][4])
{
    const int t = threadIdx.x, w = t >> 5, l = t & 31;
    const int wm = (w & 1) * 64, wn = (w >> 1) * 32;
    const int mi = l >> 3;

    gemm_fill<USE_ALO>(sb, Ahi, Alo, ar0, Bhi, Blo, br0, 0);
    CP_COMMIT();

    for (int c = 0; c < 16; ++c) {
        CP_WAIT0();
        __syncthreads();

        #pragma unroll
        for (int kt = 0; kt < 4; ++kt) {
            uint32_t ahi[4][4], alo[4][4];
            #pragma unroll
            for (int i = 0; i < 4; ++i) {
                int row = wm + 16 * i + (l & 7) + ((mi & 1) << 3);
                int u = kt * 2 + (mi >> 1);
                ldm4(ahi[i], sb + swz(row, u));
                if (USE_ALO) ldm4(alo[i], sb + 16384 + swz(row, u));
            }
            uint32_t bhi[4][2], blo[4][2];
            #pragma unroll
            for (int jp = 0; jp < 2; ++jp) {
                int row = wn + jp * 16 + ((mi >> 1) << 3) + (l & 7);
                int u = kt * 2 + (mi & 1);
                uint32_t r4[4];
                ldm4(r4, sb + 32768 + swz(row, u));
                bhi[2*jp][0] = r4[0]; bhi[2*jp][1] = r4[1];
                bhi[2*jp+1][0] = r4[2]; bhi[2*jp+1][1] = r4[3];
                ldm4(r4, sb + 49152 + swz(row, u));
                blo[2*jp][0] = r4[0]; blo[2*jp][1] = r4[1];
                blo[2*jp+1][0] = r4[2]; blo[2*jp+1][1] = r4[3];
            }
            #pragma unroll
            for (int i = 0; i < 4; ++i)
                #pragma unroll
                for (int j = 0; j < 4; ++j) {
                    mma16816(C[i][j], ahi[i], bhi[j]);
                    mma16816(C[i][j], ahi[i], blo[j]);
                    if (USE_ALO) mma16816(C[i][j], alo[i], bhi[j]);
                }
        }
        __syncthreads();
        if (c + 1 < 16) {
            gemm_fill<USE_ALO>(sb, Ahi, Alo, ar0, Bhi, Blo, br0, (c + 1) * 64);
            CP_COMMIT();
        }
    }
}

// ---------------------------------------------------------------------------
// Kernel: per-head-pair input projections. grid (32, 8, 3), 2 CTAs/SM.
// ---------------------------------------------------------------------------
__global__ __launch_bounds__(256, 2) void gemm_proj_mma()
{
    extern __shared__ char smraw[];
    uint32_t sb = (smem_u32(smraw) + 127) & ~127u;
    const int z = blockIdx.z, hp = blockIdx.y;
    const size_t row0 = (size_t)blockIdx.x * 128;

    float C[4][4][4] = {};
    const hf* Bhi = g_wthi + (size_t)(z * NH + 2 * hp) * DK * DM;
    const hf* Blo = g_wtlo + (size_t)(z * NH + 2 * hp) * DK * DM;
    if (z < 2)
        gemm_core<true >(sb, g_xhi[z], g_xlo[z], row0, Bhi, Blo, 0, C);
    else
        gemm_core<false>(sb, g_xhi[z], nullptr,  row0, Bhi, Blo, 0, C);

    const int t = threadIdx.x, w = t >> 5, l = t & 31;
    const int gid = l >> 2, tig = l & 3;
    const int wm = (w & 1) * 64, wn = (w >> 1) * 32;

    #pragma unroll
    for (int i = 0; i < 4; ++i)
        #pragma unroll
        for (int j = 0; j < 4; ++j) {
            const int col = wn + 8 * j + 2 * tig;
            const int head = 2 * hp + (col >> 6), d = col & 63;
            const size_t r0 = row0 + wm + 16 * i + gid, r1 = r0 + 8;
            const size_t b = r0 >> 11;
            const size_t hb = (size_t)head * BB + b;
            if (z == 2) {
                const size_t lq0 = r0 & 2047, lq1 = r1 & 2047;
                hf* V = g_vthi + hb * (size_t)DK * LL;
                V[(size_t)d * LL + lq0]       = __float2half_rn(C[i][j][0]);
                V[(size_t)(d + 1) * LL + lq0] = __float2half_rn(C[i][j][1]);
                V[(size_t)d * LL + lq1]       = __float2half_rn(C[i][j][2]);
                V[(size_t)(d + 1) * LL + lq1] = __float2half_rn(C[i][j][3]);
            } else {
                hf* Hi = (z == 0 ? g_qhi : g_khi);
                hf* Lo = (z == 0 ? g_qlo : g_klo);
                #pragma unroll
                for (int rr = 0; rr < 2; ++rr) {
                    const size_t r = rr ? r1 : r0;
                    const float f0 = C[i][j][2 * rr], f1 = C[i][j][2 * rr + 1];
                    uint32_t hh = pack_hf(f0, f1);
                    __half2 h2 = *(__half2*)&hh;
                    uint32_t ll = pack_hf(f0 - __half2float(h2.x),
                                          f1 - __half2float(h2.y));
                    const size_t o = (hb * LL + (r & 2047)) * DK + d;
                    *(uint32_t*)(Hi + o) = hh;
                    *(uint32_t*)(Lo + o) = ll;
                }
            }
        }
}

// ---------------------------------------------------------------------------
// Kernel: output projection + bias. grid (32, 8). 2-MMA, 2 CTAs/SM.
// ---------------------------------------------------------------------------
__global__ __launch_bounds__(256, 2) void gemm_out_mma(
    const float* __restrict__ bias, float* __restrict__ out)
{
    extern __shared__ char smraw[];
    uint32_t sb = (smem_u32(smraw) + 127) & ~127u;
    const size_t row0 = (size_t)blockIdx.x * 128;
    const size_t col0 = (size_t)blockIdx.y * 128;

    float C[4][4][4] = {};
    gemm_core<false>(sb, g_atthi, nullptr, row0, g_wphi, g_wplo, col0, C);

    const int t = threadIdx.x, w = t >> 5, l = t & 31;
    const int gid = l >> 2, tig = l & 3;
    const int wm = (w & 1) * 64, wn = (w >> 1) * 32;

    #pragma unroll
    for (int i = 0; i < 4; ++i)
        #pragma unroll
        for (int j = 0; j < 4; ++j) {
            size_t col = col0 + wn + 8 * j + 2 * tig;
            size_t r = row0 + wm + 16 * i + gid;
            float2 b2 = *(const float2*)(bias + col);
            *(float2*)(out + r * DM + col) =
                make_float2(C[i][j][0] + b2.x, C[i][j][1] + b2.y);
            *(float2*)(out + (r + 8) * DM + col) =
                make_float2(C[i][j][2] + b2.x, C[i][j][3] + b2.y);
        }
}

// ---------------------------------------------------------------------------
// Flash attention on HMMA (fp16). grid (16, 32). 128 q-rows/CTA, 64-key tiles.
// QK: 3-MMA split. PV: 1-MMA. Row sums via ones-MMA (osum accumulator) —
// removes sum FADDs + shuffles from the softmax critical path.
// 4-stage ring + fill-ahead-2, one barrier/iter. 2 CTAs/SM.
// ---------------------------------------------------------------------------
#define ATTN_STAGE 24576
#define ATTN_SMEM (16384 + 4 * ATTN_STAGE + 128)

__device__ __forceinline__ void attn_fill(uint32_t base,
    const hf* khi, const hf* klo, const hf* vthi, int j0)
{
    const int t = threadIdx.x;
    #pragma unroll
    for (int i = 0; i < 2; ++i) {
        int g = i * 256 + t;
        int row = g >> 3, u = g & 7;
        uint32_t s = swz(row, u);
        CP16(base + s,         khi  + (size_t)(j0 + row) * DK + u * 8);
        CP16(base + 8192 + s,  klo  + (size_t)(j0 + row) * DK + u * 8);
        CP16(base + 16384 + s, vthi + (size_t)row * LL + j0 + u * 8);
    }
}

__global__ __launch_bounds__(256, 2) void attn_mma()
{
    extern __shared__ char smraw[];
    const uint32_t sb = (smem_u32(smraw) + 127) & ~127u;
    const uint32_t QLO = sb, ST0 = sb + 16384;

    const int hb = blockIdx.y;
    const int h = hb >> 1, b = hb & 1;
    const int l0 = blockIdx.x * 128;
    const hf* qhi = g_qhi + (size_t)hb * LL * DK;
    const hf* qlo = g_qlo + (size_t)hb * LL * DK;
    const hf* khi = g_khi + (size_t)hb * LL * DK;
    const hf* klo = g_klo + (size_t)hb * LL * DK;
    const hf* vthi = g_vthi + (size_t)hb * DK * LL;

    const int t = threadIdx.x, w = t >> 5, l = t & 31;
    const int gid = l >> 2, tig = l & 3;
    const int mi = l >> 3;

    // Init: Q-hi staged temporarily in stage0 region; Q-lo resident at QLO.
    #pragma unroll
    for (int i = 0; i < 4; ++i) {
        int g = i * 256 + t;
        int row = g >> 3, u = g & 7;
        uint32_t s = swz(row, u);
        *(uint4*)(smraw + (ST0 - sb) + s) =
            *(const uint4*)(qhi + (size_t)(l0 + row) * DK + u * 8);
        *(uint4*)(smraw + (QLO - sb) + s) =
            *(const uint4*)(qlo + (size_t)(l0 + row) * DK + u * 8);
    }
    __syncthreads();

    uint32_t qfh[4][4];
    #pragma unroll
    for (int kt = 0; kt < 4; ++kt) {
        int row = w * 16 + (l & 7) + ((mi & 1) << 3);
        int u = kt * 2 + (mi >> 1);
        ldm4(qfh[kt], ST0 + swz(row, u));
    }
    __syncthreads();

    attn_fill(ST0, khi, klo, vthi, 0);
    CP_COMMIT();
    attn_fill(ST0 + ATTN_STAGE, khi, klo, vthi, 64);
    CP_COMMIT();

    const uint32_t ones2[2] = { 0x3C003C00u, 0x3C003C00u };   // fp16 1.0 x4

    float o[8][4] = {};
    float osum[4] = {};            // row sums via ones-MMA (cols all equal)
    float m0 = -1e30f, m1 = -1e30f;

    for (int jt = 0; jt < 32; ++jt) {
        if (jt + 2 < 32) {
            attn_fill(ST0 + ((jt + 2) & 3) * ATTN_STAGE, khi, klo, vthi,
                      (jt + 2) * 64);
            CP_COMMIT();
            CP_WAIT2();
        } else if (jt + 1 < 32) {
            CP_WAIT1();
        } else {
            CP_WAIT0();
        }
        __syncthreads();
        const uint32_t tb = ST0 + (jt & 3) * ATTN_STAGE;

        // ---- S = Q K^T (3-MMA split) ----
        float s[8][4] = {};
        #pragma unroll
        for (int kt = 0; kt < 4; ++kt) {
            uint32_t qfl[4];
            {
                int row = w * 16 + (l & 7) + ((mi & 1) << 3);
                int u = kt * 2 + (mi >> 1);
                ldm4(qfl, QLO + swz(row, u));
            }
            uint32_t kh[8][2], kl[8][2];
            #pragma unroll
            for (int jp = 0; jp < 4; ++jp) {
                int row = jp * 16 + ((mi >> 1) << 3) + (l & 7);
                int u = kt * 2 + (mi & 1);
                uint32_t r4[4];
                ldm4(r4, tb + swz(row, u));
                kh[2*jp][0] = r4[0]; kh[2*jp][1] = r4[1];
                kh[2*jp+1][0] = r4[2]; kh[2*jp+1][1] = r4[3];
                ldm4(r4, tb + 8192 + swz(row, u));
                kl[2*jp][0] = r4[0]; kl[2*jp][1] = r4[1];
                kl[2*jp+1][0] = r4[2]; kl[2*jp+1][1] = r4[3];
            }
            #pragma unroll
            for (int n = 0; n < 8; ++n) {
                mma16816(s[n], qfh[kt], kh[n]);
                mma16816(s[n], qfh[kt], kl[n]);
                mma16816(s[n], qfl,     kh[n]);
            }
        }

        // ---- online softmax: max-reduce + exp only (sum via ones-MMA) ----
        float rm0 = -1e30f, rm1 = -1e30f;
        #pragma unroll
        for (int n = 0; n < 8; ++n) {
            rm0 = fmaxf(rm0, fmaxf(s[n][0], s[n][1]));
            rm1 = fmaxf(rm1, fmaxf(s[n][2], s[n][3]));
        }
        rm0 = fmaxf(rm0, __shfl_xor_sync(0xffffffffu, rm0, 1));
        rm0 = fmaxf(rm0, __shfl_xor_sync(0xffffffffu, rm0, 2));
        rm1 = fmaxf(rm1, __shfl_xor_sync(0xffffffffu, rm1, 1));
        rm1 = fmaxf(rm1, __shfl_xor_sync(0xffffffffu, rm1, 2));
        const float mn0 = fmaxf(m0, rm0), mn1 = fmaxf(m1, rm1);
        const float sc0 = __expf(m0 - mn0), sc1 = __expf(m1 - mn1);
        m0 = mn0; m1 = mn1;
        #pragma unroll
        for (int n = 0; n < 8; ++n) {
            s[n][0] = __expf(s[n][0] - mn0); s[n][1] = __expf(s[n][1] - mn0);
            s[n][2] = __expf(s[n][2] - mn1); s[n][3] = __expf(s[n][3] - mn1);
        }
        #pragma unroll
        for (int n = 0; n < 8; ++n) {
            o[n][0] *= sc0; o[n][1] *= sc0;
            o[n][2] *= sc1; o[n][3] *= sc1;
        }
        osum[0] *= sc0; osum[1] *= sc0;
        osum[2] *= sc1; osum[3] *= sc1;

        // ---- P (hi) x V (hi) + ones-MMA row sums ----
        #pragma unroll
        for (int kt = 0; kt < 4; ++kt) {
            uint32_t pah[4] = {
                pack_hf(s[2*kt][0],   s[2*kt][1]),
                pack_hf(s[2*kt][2],   s[2*kt][3]),
                pack_hf(s[2*kt+1][0], s[2*kt+1][1]),
                pack_hf(s[2*kt+1][2], s[2*kt+1][3]) };
            mma16816(osum, pah, ones2);
            uint32_t vh[8][2];
            #pragma unroll
            for (int jp = 0; jp < 4; ++jp) {
                int row = jp * 16 + ((mi >> 1) << 3) + (l & 7);
                int u = kt * 2 + (mi & 1);
                uint32_t r4[4];
                ldm4(r4, tb + 16384 + swz(row, u));
                vh[2*jp][0] = r4[0]; vh[2*jp][1] = r4[1];
                vh[2*jp+1][0] = r4[2]; vh[2*jp+1][1] = r4[3];
            }
            #pragma unroll
            for (int n = 0; n < 8; ++n)
                mma16816(o[n], pah, vh[n]);
        }
    }

    // ---- epilogue: (o / l) * q -> fp16 hi ; l = osum (cols identical) ----
    const float inv0 = 1.0f / osum[0], inv1 = 1.0f / osum[2];
    const size_t r0 = l0 + w * 16 + gid, r1 = r0 + 8;
    #pragma unroll
    for (int n = 0; n < 8; ++n) {
        const int d = 8 * n + 2 * tig;
        __half2 qh2a = *(const __half2*)(qhi + r0 * DK + d);
        __half2 ql2a = *(const __half2*)(qlo + r0 * DK + d);
        __half2 qh2b = *(const __half2*)(qhi + r1 * DK + d);
        __half2 ql2b = *(const __half2*)(qlo + r1 * DK + d);
        float qa0 = __half2float(qh2a.x) + __half2float(ql2a.x);
        float qa1 = __half2float(qh2a.y) + __half2float(ql2a.y);
        float qb0 = __half2float(qh2b.x) + __half2float(ql2b.x);
        float qb1 = __half2float(qh2b.y) + __half2float(ql2b.y);
        float v00 = o[n][0] * inv0 * qa0, v01 = o[n][1] * inv0 * qa1;
        float v10 = o[n][2] * inv1 * qb0, v11 = o[n][3] * inv1 * qb1;

        size_t o0 = ((size_t)b * LL + r0) * DM + h * DK + d;
        size_t o1 = ((size_t)b * LL + r1) * DM + h * DK + d;
        *(uint32_t*)(g_atthi + o0) = pack_hf(v00, v01);
        *(uint32_t*)(g_atthi + o1) = pack_hf(v10, v11);
    }
}

// ---------------------------------------------------------------------------
extern "C" void kernel_launch(void* const* d_in, const int* in_sizes, int n_in,
                              void* d_out, int out_size)
{
    const float* q  = (const float*)d_in[0];
    const float* k  = (const float*)d_in[1];
    const float* v  = (const float*)d_in[2];
    const float* wq = (const float*)d_in[3];
    const float* wk = (const float*)d_in[4];
    const float* wv = (const float*)d_in[5];
    const float* wp = (const float*)d_in[6];
    const float* bp = (const float*)d_in[7];
    float* out = (float*)d_out;

    cudaFuncSetAttribute(gemm_proj_mma,
                         cudaFuncAttributeMaxDynamicSharedMemorySize, GEMM_SMEM);
    cudaFuncSetAttribute(gemm_out_mma,
                         cudaFuncAttributeMaxDynamicSharedMemorySize, GEMM_SMEM);
    cudaFuncSetAttribute(attn_mma,
                         cudaFuncAttributeMaxDynamicSharedMemorySize, ATTN_SMEM);

    const int n4x = MROWS * DM / 4;
    conv_split_kernel<<<dim3((n4x + 255) / 256, 4), 256>>>(q, k, v, wp);
    conv_wt_kernel<<<dim3(NH, 3), 256>>>(wq, wk, wv);

    gemm_proj_mma<<<dim3(MROWS / 128, NH / 2, 3), 256, GEMM_SMEM>>>();

    attn_mma<<<dim3(LL / 128, NH * BB), 256, ATTN_SMEM>>>();

    gemm_out_mma<<<dim3(MROWS / 128, DM / 128), 256, GEMM_SMEM>>>(bp, out);
}

// round 13
// speedup vs baseline: 1.0256x; 1.0235x over previous
#include <cuda_runtime.h>
#include <cuda_fp16.h>
#include <cstdint>

#define BB 2
#define LL 2048
#define DM 1024
#define NH 16
#define DK 64
#define MROWS (BB * LL)   // 4096

typedef __half hf;

// ---------------------------------------------------------------------------
// Global scratch (no allocations allowed)
// ---------------------------------------------------------------------------
__device__ hf g_xhi[3][MROWS * DM];             // split inputs q,k,v (v: hi only)
__device__ hf g_xlo[3][MROWS * DM];
__device__ hf g_wthi[3 * NH * DK * DM];         // W transposed [z][h][n][k]
__device__ hf g_wtlo[3 * NH * DK * DM];
__device__ hf g_wphi[DM * DM];                  // w_proj [n][k]
__device__ hf g_wplo[DM * DM];

__device__ hf g_qhi[NH * BB * LL * DK];         // [hb][l][k]
__device__ hf g_qlo[NH * BB * LL * DK];
__device__ hf g_khi[NH * BB * LL * DK];
__device__ hf g_klo[NH * BB * LL * DK];
__device__ hf g_vthi[NH * BB * DK * LL];        // [hb][d][l]  (V transposed, hi only)

__device__ hf g_atthi[MROWS * DM];              // attention output (hi only)

// ---------------------------------------------------------------------------
// PTX helpers (base-ISA: mma.sync / ldmatrix / cp.async)
// ---------------------------------------------------------------------------
__device__ __forceinline__ uint32_t smem_u32(const void* p) {
    uint32_t a;
    asm("{ .reg .u64 t; cvta.to.shared.u64 t, %1; cvt.u32.u64 %0, t; }"
        : "=r"(a) : "l"(p));
    return a;
}
__device__ __forceinline__ void ldm4(uint32_t r[4], uint32_t a) {
    asm volatile("ldmatrix.sync.aligned.m8n8.x4.shared.b16 {%0,%1,%2,%3}, [%4];"
        : "=r"(r[0]), "=r"(r[1]), "=r"(r[2]), "=r"(r[3]) : "r"(a));
}
__device__ __forceinline__ void mma16816(float c[4], const uint32_t a[4],
                                         const uint32_t b[2]) {
    asm volatile("mma.sync.aligned.m16n8k16.row.col.f32.f16.f16.f32 "
        "{%0,%1,%2,%3}, {%4,%5,%6,%7}, {%8,%9}, {%0,%1,%2,%3};"
        : "+f"(c[0]), "+f"(c[1]), "+f"(c[2]), "+f"(c[3])
        : "r"(a[0]), "r"(a[1]), "r"(a[2]), "r"(a[3]), "r"(b[0]), "r"(b[1]));
}
#define CP16(dst, src) \
    asm volatile("cp.async.cg.shared.global [%0], [%1], 16;" \
                 :: "r"(dst), "l"(src) : "memory")
#define CP_COMMIT() asm volatile("cp.async.commit_group;" ::: "memory")
#define CP_WAIT2()  asm volatile("cp.async.wait_group 2;" ::: "memory")
#define CP_WAIT1()  asm volatile("cp.async.wait_group 1;" ::: "memory")
#define CP_WAIT0()  asm volatile("cp.async.wait_group 0;" ::: "memory")

// 128B-row tile swizzle: unit = 16B column, XOR by row&7 (conflict-free ldmatrix)
__device__ __forceinline__ uint32_t swz(int row, int u) {
    return (uint32_t)(row * 128 + ((u ^ (row & 7)) << 4));
}
// pack two fp32 into f16x2 (first arg -> low half)
__device__ __forceinline__ uint32_t pack_hf(float lo, float hi) {
    uint32_t r;
    asm("cvt.rn.f16x2.f32 %0, %1, %2;" : "=r"(r) : "f"(hi), "f"(lo));
    return r;
}
// packed fp16x2 exp2
__device__ __forceinline__ uint32_t ex2_f16x2(uint32_t x) {
    uint32_t r;
    asm("ex2.approx.f16x2 %0, %1;" : "=r"(r) : "r"(x));
    return r;
}

// ---------------------------------------------------------------------------
// Conversion kernels (unchanged)
// ---------------------------------------------------------------------------
__global__ void conv_split_kernel(const float* __restrict__ q,
                                  const float* __restrict__ k,
                                  const float* __restrict__ v,
                                  const float* __restrict__ wp)
{
    const int sel = blockIdx.y;
    const float* src;
    hf *hi, *lo;
    bool wlo = true;
    int n4;
    if      (sel == 0) { src = q;  hi = g_xhi[0]; lo = g_xlo[0]; n4 = MROWS * DM / 4; }
    else if (sel == 1) { src = k;  hi = g_xhi[1]; lo = g_xlo[1]; n4 = MROWS * DM / 4; }
    else if (sel == 2) { src = v;  hi = g_xhi[2]; lo = nullptr;  n4 = MROWS * DM / 4; wlo = false; }
    else               { src = wp; hi = g_wphi;   lo = g_wplo;   n4 = DM * DM / 4; }

    int i = blockIdx.x * 256 + threadIdx.x;
    if (i >= n4) return;
    float4 vv = ((const float4*)src)[i];
    uint32_t h01 = pack_hf(vv.x, vv.y);
    uint32_t h23 = pack_hf(vv.z, vv.w);
    ((uint32_t*)hi)[2 * i]     = h01;
    ((uint32_t*)hi)[2 * i + 1] = h23;
    if (wlo) {
        __half2 f01 = *(__half2*)&h01, f23 = *(__half2*)&h23;
        ((uint32_t*)lo)[2 * i] =
            pack_hf(vv.x - __half2float(f01.x), vv.y - __half2float(f01.y));
        ((uint32_t*)lo)[2 * i + 1] =
            pack_hf(vv.z - __half2float(f23.x), vv.w - __half2float(f23.y));
    }
}

__global__ void conv_wt_kernel(const float* __restrict__ wq,
                               const float* __restrict__ wk,
                               const float* __restrict__ wv)
{
    __shared__ float ts[64][65];
    const int h = blockIdx.x, z = blockIdx.y;
    const float* W = (z == 0 ? wq : z == 1 ? wk : wv) + (size_t)h * DM * DK;
    hf* hi = g_wthi + (size_t)(z * NH + h) * DK * DM;
    hf* lo = g_wtlo + (size_t)(z * NH + h) * DK * DM;
    const int t = threadIdx.x;
    for (int k0 = 0; k0 < DM; k0 += 64) {
        __syncthreads();
        for (int i = 0; i < 16; ++i) {
            int idx = i * 256 + t;
            int r = idx >> 6, c = idx & 63;
            ts[r][c] = W[(size_t)(k0 + r) * DK + c];
        }
        __syncthreads();
        for (int i = 0; i < 16; ++i) {
            int idx = i * 256 + t;
            int n = idx >> 6, c = idx & 63;
            float x = ts[c][n];
            hf h0 = __float2half_rn(x);
            hi[(size_t)n * DM + k0 + c] = h0;
            lo[(size_t)n * DM + k0 + c] = __float2half_rn(x - __half2float(h0));
        }
    }
}

// ---------------------------------------------------------------------------
// GEMM core (R7 config — best measured): single 64KB stage, 2 CTAs/SM;
// co-resident CTA hides fill latency. USE_ALO: 3-MMA split; else 2-MMA.
// ---------------------------------------------------------------------------
#define GEMM_SMEM (65536 + 128)

template <bool USE_ALO>
__device__ __forceinline__ void gemm_fill(uint32_t base,
    const hf* __restrict__ Ahi, const hf* __restrict__ Alo, size_t ar0,
    const hf* __restrict__ Bhi, const hf* __restrict__ Blo, size_t br0,
    int k0)
{
    const int t = threadIdx.x;
    #pragma unroll
    for (int i = 0; i < 4; ++i) {
        int g = i * 256 + t;
        int row = g >> 3, u = g & 7;
        size_t goff = (size_t)row * DM + k0 + u * 8;
        uint32_t s = swz(row, u);
        CP16(base + s, Ahi + (size_t)ar0 * DM + goff);
        if (USE_ALO) CP16(base + 16384 + s, Alo + (size_t)ar0 * DM + goff);
        CP16(base + 32768 + s, Bhi + (size_t)br0 * DM + goff);
        CP16(base + 49152 + s, Blo + (size_t)br0 * DM + goff);
    }
}

template <bool USE_ALO>
__device__ __forceinline__ void gemm_core(uint32_t sb,
    const hf* Ahi, const hf* Alo, size_t ar0,
    const hf* Bhi, const hf* Blo, size_t br0,
    float C[4][4][4])
{
    const int t = threadIdx.x, w = t >> 5, l = t & 31;
    const int wm = (w & 1) * 64, wn = (w >> 1) * 32;
    const int mi = l >> 3;

    gemm_fill<USE_ALO>(sb, Ahi, Alo, ar0, Bhi, Blo, br0, 0);
    CP_COMMIT();

    for (int c = 0; c < 16; ++c) {
        CP_WAIT0();
        __syncthreads();

        #pragma unroll
        for (int kt = 0; kt < 4; ++kt) {
            uint32_t ahi[4][4], alo[4][4];
            #pragma unroll
            for (int i = 0; i < 4; ++i) {
                int row = wm + 16 * i + (l & 7) + ((mi & 1) << 3);
                int u = kt * 2 + (mi >> 1);
                ldm4(ahi[i], sb + swz(row, u));
                if (USE_ALO) ldm4(alo[i], sb + 16384 + swz(row, u));
            }
            uint32_t bhi[4][2], blo[4][2];
            #pragma unroll
            for (int jp = 0; jp < 2; ++jp) {
                int row = wn + jp * 16 + ((mi >> 1) << 3) + (l & 7);
                int u = kt * 2 + (mi & 1);
                uint32_t r4[4];
                ldm4(r4, sb + 32768 + swz(row, u));
                bhi[2*jp][0] = r4[0]; bhi[2*jp][1] = r4[1];
                bhi[2*jp+1][0] = r4[2]; bhi[2*jp+1][1] = r4[3];
                ldm4(r4, sb + 49152 + swz(row, u));
                blo[2*jp][0] = r4[0]; blo[2*jp][1] = r4[1];
                blo[2*jp+1][0] = r4[2]; blo[2*jp+1][1] = r4[3];
            }
            #pragma unroll
            for (int i = 0; i < 4; ++i)
                #pragma unroll
                for (int j = 0; j < 4; ++j) {
                    mma16816(C[i][j], ahi[i], bhi[j]);
                    mma16816(C[i][j], ahi[i], blo[j]);
                    if (USE_ALO) mma16816(C[i][j], alo[i], bhi[j]);
                }
        }
        __syncthreads();
        if (c + 1 < 16) {
            gemm_fill<USE_ALO>(sb, Ahi, Alo, ar0, Bhi, Blo, br0, (c + 1) * 64);
            CP_COMMIT();
        }
    }
}

// ---------------------------------------------------------------------------
// Kernel: per-head-pair input projections. grid (32, 8, 3), 2 CTAs/SM.
// ---------------------------------------------------------------------------
__global__ __launch_bounds__(256, 2) void gemm_proj_mma()
{
    extern __shared__ char smraw[];
    uint32_t sb = (smem_u32(smraw) + 127) & ~127u;
    const int z = blockIdx.z, hp = blockIdx.y;
    const size_t row0 = (size_t)blockIdx.x * 128;

    float C[4][4][4] = {};
    const hf* Bhi = g_wthi + (size_t)(z * NH + 2 * hp) * DK * DM;
    const hf* Blo = g_wtlo + (size_t)(z * NH + 2 * hp) * DK * DM;
    if (z < 2)
        gemm_core<true >(sb, g_xhi[z], g_xlo[z], row0, Bhi, Blo, 0, C);
    else
        gemm_core<false>(sb, g_xhi[z], nullptr,  row0, Bhi, Blo, 0, C);

    const int t = threadIdx.x, w = t >> 5, l = t & 31;
    const int gid = l >> 2, tig = l & 3;
    const int wm = (w & 1) * 64, wn = (w >> 1) * 32;

    #pragma unroll
    for (int i = 0; i < 4; ++i)
        #pragma unroll
        for (int j = 0; j < 4; ++j) {
            const int col = wn + 8 * j + 2 * tig;
            const int head = 2 * hp + (col >> 6), d = col & 63;
            const size_t r0 = row0 + wm + 16 * i + gid, r1 = r0 + 8;
            const size_t b = r0 >> 11;
            const size_t hb = (size_t)head * BB + b;
            if (z == 2) {
                const size_t lq0 = r0 & 2047, lq1 = r1 & 2047;
                hf* V = g_vthi + hb * (size_t)DK * LL;
                V[(size_t)d * LL + lq0]       = __float2half_rn(C[i][j][0]);
                V[(size_t)(d + 1) * LL + lq0] = __float2half_rn(C[i][j][1]);
                V[(size_t)d * LL + lq1]       = __float2half_rn(C[i][j][2]);
                V[(size_t)(d + 1) * LL + lq1] = __float2half_rn(C[i][j][3]);
            } else {
                hf* Hi = (z == 0 ? g_qhi : g_khi);
                hf* Lo = (z == 0 ? g_qlo : g_klo);
                #pragma unroll
                for (int rr = 0; rr < 2; ++rr) {
                    const size_t r = rr ? r1 : r0;
                    const float f0 = C[i][j][2 * rr], f1 = C[i][j][2 * rr + 1];
                    uint32_t hh = pack_hf(f0, f1);
                    __half2 h2 = *(__half2*)&hh;
                    uint32_t ll = pack_hf(f0 - __half2float(h2.x),
                                          f1 - __half2float(h2.y));
                    const size_t o = (hb * LL + (r & 2047)) * DK + d;
                    *(uint32_t*)(Hi + o) = hh;
                    *(uint32_t*)(Lo + o) = ll;
                }
            }
        }
}

// ---------------------------------------------------------------------------
// Kernel: output projection + bias. grid (32, 8). 2-MMA, 2 CTAs/SM.
// ---------------------------------------------------------------------------
__global__ __launch_bounds__(256, 2) void gemm_out_mma(
    const float* __restrict__ bias, float* __restrict__ out)
{
    extern __shared__ char smraw[];
    uint32_t sb = (smem_u32(smraw) + 127) & ~127u;
    const size_t row0 = (size_t)blockIdx.x * 128;
    const size_t col0 = (size_t)blockIdx.y * 128;

    float C[4][4][4] = {};
    gemm_core<false>(sb, g_atthi, nullptr, row0, g_wphi, g_wplo, col0, C);

    const int t = threadIdx.x, w = t >> 5, l = t & 31;
    const int gid = l >> 2, tig = l & 3;
    const int wm = (w & 1) * 64, wn = (w >> 1) * 32;

    #pragma unroll
    for (int i = 0; i < 4; ++i)
        #pragma unroll
        for (int j = 0; j < 4; ++j) {
            size_t col = col0 + wn + 8 * j + 2 * tig;
            size_t r = row0 + wm + 16 * i + gid;
            float2 b2 = *(const float2*)(bias + col);
            *(float2*)(out + r * DM + col) =
                make_float2(C[i][j][0] + b2.x, C[i][j][1] + b2.y);
            *(float2*)(out + (r + 8) * DM + col) =
                make_float2(C[i][j][2] + b2.x, C[i][j][3] + b2.y);
        }
}

// ---------------------------------------------------------------------------
// Flash attention on HMMA (fp16). grid (16, 32). 128 q-rows/CTA, 64-key tiles.
// QK: 3-MMA split. PV: 1-MMA + ones-MMA row sums.
// Softmax exp via ex2.approx.f16x2: p = 2^(s*log2e - m*log2e) computed packed,
// output IS the fp16x2 A-fragment (halves MUFU load, deletes the pack step).
// 4-stage ring + fill-ahead-2, one barrier/iter. 2 CTAs/SM.
// ---------------------------------------------------------------------------
#define ATTN_STAGE 24576
#define ATTN_SMEM (16384 + 4 * ATTN_STAGE + 128)

__device__ __forceinline__ void attn_fill(uint32_t base,
    const hf* khi, const hf* klo, const hf* vthi, int j0)
{
    const int t = threadIdx.x;
    #pragma unroll
    for (int i = 0; i < 2; ++i) {
        int g = i * 256 + t;
        int row = g >> 3, u = g & 7;
        uint32_t s = swz(row, u);
        CP16(base + s,         khi  + (size_t)(j0 + row) * DK + u * 8);
        CP16(base + 8192 + s,  klo  + (size_t)(j0 + row) * DK + u * 8);
        CP16(base + 16384 + s, vthi + (size_t)row * LL + j0 + u * 8);
    }
}

__global__ __launch_bounds__(256, 2) void attn_mma()
{
    extern __shared__ char smraw[];
    const uint32_t sb = (smem_u32(smraw) + 127) & ~127u;
    const uint32_t QLO = sb, ST0 = sb + 16384;

    const int hb = blockIdx.y;
    const int h = hb >> 1, b = hb & 1;
    const int l0 = blockIdx.x * 128;
    const hf* qhi = g_qhi + (size_t)hb * LL * DK;
    const hf* qlo = g_qlo + (size_t)hb * LL * DK;
    const hf* khi = g_khi + (size_t)hb * LL * DK;
    const hf* klo = g_klo + (size_t)hb * LL * DK;
    const hf* vthi = g_vthi + (size_t)hb * DK * LL;

    const int t = threadIdx.x, w = t >> 5, l = t & 31;
    const int gid = l >> 2, tig = l & 3;
    const int mi = l >> 3;

    // Init: Q-hi staged temporarily in stage0 region; Q-lo resident at QLO.
    #pragma unroll
    for (int i = 0; i < 4; ++i) {
        int g = i * 256 + t;
        int row = g >> 3, u = g & 7;
        uint32_t s = swz(row, u);
        *(uint4*)(smraw + (ST0 - sb) + s) =
            *(const uint4*)(qhi + (size_t)(l0 + row) * DK + u * 8);
        *(uint4*)(smraw + (QLO - sb) + s) =
            *(const uint4*)(qlo + (size_t)(l0 + row) * DK + u * 8);
    }
    __syncthreads();

    uint32_t qfh[4][4];
    #pragma unroll
    for (int kt = 0; kt < 4; ++kt) {
        int row = w * 16 + (l & 7) + ((mi & 1) << 3);
        int u = kt * 2 + (mi >> 1);
        ldm4(qfh[kt], ST0 + swz(row, u));
    }
    __syncthreads();

    attn_fill(ST0, khi, klo, vthi, 0);
    CP_COMMIT();
    attn_fill(ST0 + ATTN_STAGE, khi, klo, vthi, 64);
    CP_COMMIT();

    const uint32_t ones2[2] = { 0x3C003C00u, 0x3C003C00u };   // fp16 1.0 x4
    const float L2E = 1.4426950408889634f;

    float o[8][4] = {};
    float osum[4] = {};            // row sums via ones-MMA (cols all equal)
    float m0 = -1e30f, m1 = -1e30f;

    for (int jt = 0; jt < 32; ++jt) {
        if (jt + 2 < 32) {
            attn_fill(ST0 + ((jt + 2) & 3) * ATTN_STAGE, khi, klo, vthi,
                      (jt + 2) * 64);
            CP_COMMIT();
            CP_WAIT2();
        } else if (jt + 1 < 32) {
            CP_WAIT1();
        } else {
            CP_WAIT0();
        }
        __syncthreads();
        const uint32_t tb = ST0 + (jt & 3) * ATTN_STAGE;

        // ---- S = Q K^T (3-MMA split) ----
        float s[8][4] = {};
        #pragma unroll
        for (int kt = 0; kt < 4; ++kt) {
            uint32_t qfl[4];
            {
                int row = w * 16 + (l & 7) + ((mi & 1) << 3);
                int u = kt * 2 + (mi >> 1);
                ldm4(qfl, QLO + swz(row, u));
            }
            uint32_t kh[8][2], kl[8][2];
            #pragma unroll
            for (int jp = 0; jp < 4; ++jp) {
                int row = jp * 16 + ((mi >> 1) << 3) + (l & 7);
                int u = kt * 2 + (mi & 1);
                uint32_t r4[4];
                ldm4(r4, tb + swz(row, u));
                kh[2*jp][0] = r4[0]; kh[2*jp][1] = r4[1];
                kh[2*jp+1][0] = r4[2]; kh[2*jp+1][1] = r4[3];
                ldm4(r4, tb + 8192 + swz(row, u));
                kl[2*jp][0] = r4[0]; kl[2*jp][1] = r4[1];
                kl[2*jp+1][0] = r4[2]; kl[2*jp+1][1] = r4[3];
            }
            #pragma unroll
            for (int n = 0; n < 8; ++n) {
                mma16816(s[n], qfh[kt], kh[n]);
                mma16816(s[n], qfh[kt], kl[n]);
                mma16816(s[n], qfl,     kh[n]);
            }
        }

        // ---- online softmax: max-reduce, then packed fp16x2 ex2 ----
        float rm0 = -1e30f, rm1 = -1e30f;
        #pragma unroll
        for (int n = 0; n < 8; ++n) {
            rm0 = fmaxf(rm0, fmaxf(s[n][0], s[n][1]));
            rm1 = fmaxf(rm1, fmaxf(s[n][2], s[n][3]));
        }
        rm0 = fmaxf(rm0, __shfl_xor_sync(0xffffffffu, rm0, 1));
        rm0 = fmaxf(rm0, __shfl_xor_sync(0xffffffffu, rm0, 2));
        rm1 = fmaxf(rm1, __shfl_xor_sync(0xffffffffu, rm1, 1));
        rm1 = fmaxf(rm1, __shfl_xor_sync(0xffffffffu, rm1, 2));
        const float mn0 = fmaxf(m0, rm0), mn1 = fmaxf(m1, rm1);
        const float sc0 = __expf(m0 - mn0), sc1 = __expf(m1 - mn1);
        m0 = mn0; m1 = mn1;
        const float mn0L = mn0 * L2E, mn1L = mn1 * L2E;

        // p packed fp16x2 directly: pp[n][0] = p(cols 0,1), pp[n][1] = p(cols 2,3)
        uint32_t pp[8][2];
        #pragma unroll
        for (int n = 0; n < 8; ++n) {
            pp[n][0] = ex2_f16x2(pack_hf(fmaf(s[n][0], L2E, -mn0L),
                                         fmaf(s[n][1], L2E, -mn0L)));
            pp[n][1] = ex2_f16x2(pack_hf(fmaf(s[n][2], L2E, -mn1L),
                                         fmaf(s[n][3], L2E, -mn1L)));
        }
        #pragma unroll
        for (int n = 0; n < 8; ++n) {
            o[n][0] *= sc0; o[n][1] *= sc0;
            o[n][2] *= sc1; o[n][3] *= sc1;
        }
        osum[0] *= sc0; osum[1] *= sc0;
        osum[2] *= sc1; osum[3] *= sc1;

        // ---- P (fp16x2) x V (hi) + ones-MMA row sums ----
        #pragma unroll
        for (int kt = 0; kt < 4; ++kt) {
            uint32_t pah[4] = { pp[2*kt][0], pp[2*kt][1],
                                pp[2*kt+1][0], pp[2*kt+1][1] };
            mma16816(osum, pah, ones2);
            uint32_t vh[8][2];
            #pragma unroll
            for (int jp = 0; jp < 4; ++jp) {
                int row = jp * 16 + ((mi >> 1) << 3) + (l & 7);
                int u = kt * 2 + (mi & 1);
                uint32_t r4[4];
                ldm4(r4, tb + 16384 + swz(row, u));
                vh[2*jp][0] = r4[0]; vh[2*jp][1] = r4[1];
                vh[2*jp+1][0] = r4[2]; vh[2*jp+1][1] = r4[3];
            }
            #pragma unroll
            for (int n = 0; n < 8; ++n)
                mma16816(o[n], pah, vh[n]);
        }
    }

    // ---- epilogue: (o / l) * q -> fp16 hi ; l = osum (cols identical) ----
    const float inv0 = 1.0f / osum[0], inv1 = 1.0f / osum[2];
    const size_t r0 = l0 + w * 16 + gid, r1 = r0 + 8;
    #pragma unroll
    for (int n = 0; n < 8; ++n) {
        const int d = 8 * n + 2 * tig;
        __half2 qh2a = *(const __half2*)(qhi + r0 * DK + d);
        __half2 ql2a = *(const __half2*)(qlo + r0 * DK + d);
        __half2 qh2b = *(const __half2*)(qhi + r1 * DK + d);
        __half2 ql2b = *(const __half2*)(qlo + r1 * DK + d);
        float qa0 = __half2float(qh2a.x) + __half2float(ql2a.x);
        float qa1 = __half2float(qh2a.y) + __half2float(ql2a.y);
        float qb0 = __half2float(qh2b.x) + __half2float(ql2b.x);
        float qb1 = __half2float(qh2b.y) + __half2float(ql2b.y);
        float v00 = o[n][0] * inv0 * qa0, v01 = o[n][1] * inv0 * qa1;
        float v10 = o[n][2] * inv1 * qb0, v11 = o[n][3] * inv1 * qb1;

        size_t o0 = ((size_t)b * LL + r0) * DM + h * DK + d;
        size_t o1 = ((size_t)b * LL + r1) * DM + h * DK + d;
        *(uint32_t*)(g_atthi + o0) = pack_hf(v00, v01);
        *(uint32_t*)(g_atthi + o1) = pack_hf(v10, v11);
    }
}

// ---------------------------------------------------------------------------
extern "C" void kernel_launch(void* const* d_in, const int* in_sizes, int n_in,
                              void* d_out, int out_size)
{
    const float* q  = (const float*)d_in[0];
    const float* k  = (const float*)d_in[1];
    const float* v  = (const float*)d_in[2];
    const float* wq = (const float*)d_in[3];
    const float* wk = (const float*)d_in[4];
    const float* wv = (const float*)d_in[5];
    const float* wp = (const float*)d_in[6];
    const float* bp = (const float*)d_in[7];
    float* out = (float*)d_out;

    cudaFuncSetAttribute(gemm_proj_mma,
                         cudaFuncAttributeMaxDynamicSharedMemorySize, GEMM_SMEM);
    cudaFuncSetAttribute(gemm_out_mma,
                         cudaFuncAttributeMaxDynamicSharedMemorySize, GEMM_SMEM);
    cudaFuncSetAttribute(attn_mma,
                         cudaFuncAttributeMaxDynamicSharedMemorySize, ATTN_SMEM);

    const int n4x = MROWS * DM / 4;
    conv_split_kernel<<<dim3((n4x + 255) / 256, 4), 256>>>(q, k, v, wp);
    conv_wt_kernel<<<dim3(NH, 3), 256>>>(wq, wk, wv);

    gemm_proj_mma<<<dim3(MROWS / 128, NH / 2, 3), 256, GEMM_SMEM>>>();

    attn_mma<<<dim3(LL / 128, NH * BB), 256, ATTN_SMEM>>>();

    gemm_out_mma<<<dim3(MROWS / 128, DM / 128), 256, GEMM_SMEM>>>(bp, out);
}

// round 14
// speedup vs baseline: 1.1237x; 1.0957x over previous
#include <cuda_runtime.h>
#include <cuda_fp16.h>
#include <cstdint>

#define BB 2
#define LL 2048
#define DM 1024
#define NH 16
#define DK 64
#define MROWS (BB * LL)   // 4096

typedef __half hf;

// ---------------------------------------------------------------------------
// Global scratch (no allocations allowed)
// ---------------------------------------------------------------------------
__device__ hf g_xhi[3][MROWS * DM];             // split inputs q,k,v (v: hi only)
__device__ hf g_xlo[3][MROWS * DM];
__device__ hf g_wthi[3 * NH * DK * DM];         // W transposed [z][h][n][k]
__device__ hf g_wtlo[3 * NH * DK * DM];
__device__ hf g_wphi[DM * DM];                  // w_proj [n][k] (hi only)

__device__ hf g_qhi[NH * BB * LL * DK];         // [hb][l][k]
__device__ hf g_qlo[NH * BB * LL * DK];
__device__ hf g_khi[NH * BB * LL * DK];
__device__ hf g_klo[NH * BB * LL * DK];
__device__ hf g_vthi[NH * BB * DK * LL];        // [hb][d][l]  (V transposed, hi only)

__device__ hf g_atthi[MROWS * DM];              // attention output (hi only)

// ---------------------------------------------------------------------------
// PTX helpers (base-ISA: mma.sync / ldmatrix / cp.async)
// ---------------------------------------------------------------------------
__device__ __forceinline__ uint32_t smem_u32(const void* p) {
    uint32_t a;
    asm("{ .reg .u64 t; cvta.to.shared.u64 t, %1; cvt.u32.u64 %0, t; }"
        : "=r"(a) : "l"(p));
    return a;
}
__device__ __forceinline__ void ldm4(uint32_t r[4], uint32_t a) {
    asm volatile("ldmatrix.sync.aligned.m8n8.x4.shared.b16 {%0,%1,%2,%3}, [%4];"
        : "=r"(r[0]), "=r"(r[1]), "=r"(r[2]), "=r"(r[3]) : "r"(a));
}
__device__ __forceinline__ void mma16816(float c[4], const uint32_t a[4],
                                         const uint32_t b[2]) {
    asm volatile("mma.sync.aligned.m16n8k16.row.col.f32.f16.f16.f32 "
        "{%0,%1,%2,%3}, {%4,%5,%6,%7}, {%8,%9}, {%0,%1,%2,%3};"
        : "+f"(c[0]), "+f"(c[1]), "+f"(c[2]), "+f"(c[3])
        : "r"(a[0]), "r"(a[1]), "r"(a[2]), "r"(a[3]), "r"(b[0]), "r"(b[1]));
}
#define CP16(dst, src) \
    asm volatile("cp.async.cg.shared.global [%0], [%1], 16;" \
                 :: "r"(dst), "l"(src) : "memory")
#define CP_COMMIT() asm volatile("cp.async.commit_group;" ::: "memory")
#define CP_WAIT2()  asm volatile("cp.async.wait_group 2;" ::: "memory")
#define CP_WAIT1()  asm volatile("cp.async.wait_group 1;" ::: "memory")
#define CP_WAIT0()  asm volatile("cp.async.wait_group 0;" ::: "memory")

// 128B-row tile swizzle: unit = 16B column, XOR by row&7 (conflict-free ldmatrix)
__device__ __forceinline__ uint32_t swz(int row, int u) {
    return (uint32_t)(row * 128 + ((u ^ (row & 7)) << 4));
}
// pack two fp32 into f16x2 (first arg -> low half)
__device__ __forceinline__ uint32_t pack_hf(float lo, float hi) {
    uint32_t r;
    asm("cvt.rn.f16x2.f32 %0, %1, %2;" : "=r"(r) : "f"(hi), "f"(lo));
    return r;
}
// packed fp16x2 exp2
__device__ __forceinline__ uint32_t ex2_f16x2(uint32_t x) {
    uint32_t r;
    asm("ex2.approx.f16x2 %0, %1;" : "=r"(r) : "r"(x));
    return r;
}

// ---------------------------------------------------------------------------
// Conversion kernels
// ---------------------------------------------------------------------------
__global__ void conv_split_kernel(const float* __restrict__ q,
                                  const float* __restrict__ k,
                                  const float* __restrict__ v,
                                  const float* __restrict__ wp)
{
    const int sel = blockIdx.y;
    const float* src;
    hf *hi, *lo;
    bool wlo = true;
    int n4;
    if      (sel == 0) { src = q;  hi = g_xhi[0]; lo = g_xlo[0]; n4 = MROWS * DM / 4; }
    else if (sel == 1) { src = k;  hi = g_xhi[1]; lo = g_xlo[1]; n4 = MROWS * DM / 4; }
    else if (sel == 2) { src = v;  hi = g_xhi[2]; lo = nullptr;  n4 = MROWS * DM / 4; wlo = false; }
    else               { src = wp; hi = g_wphi;   lo = nullptr;  n4 = DM * DM / 4;    wlo = false; }

    int i = blockIdx.x * 256 + threadIdx.x;
    if (i >= n4) return;
    float4 vv = ((const float4*)src)[i];
    uint32_t h01 = pack_hf(vv.x, vv.y);
    uint32_t h23 = pack_hf(vv.z, vv.w);
    ((uint32_t*)hi)[2 * i]     = h01;
    ((uint32_t*)hi)[2 * i + 1] = h23;
    if (wlo) {
        __half2 f01 = *(__half2*)&h01, f23 = *(__half2*)&h23;
        ((uint32_t*)lo)[2 * i] =
            pack_hf(vv.x - __half2float(f01.x), vv.y - __half2float(f01.y));
        ((uint32_t*)lo)[2 * i + 1] =
            pack_hf(vv.z - __half2float(f23.x), vv.w - __half2float(f23.y));
    }
}

__global__ void conv_wt_kernel(const float* __restrict__ wq,
                               const float* __restrict__ wk,
                               const float* __restrict__ wv)
{
    __shared__ float ts[64][65];
    const int h = blockIdx.x, z = blockIdx.y;
    const float* W = (z == 0 ? wq : z == 1 ? wk : wv) + (size_t)h * DM * DK;
    hf* hi = g_wthi + (size_t)(z * NH + h) * DK * DM;
    hf* lo = g_wtlo + (size_t)(z * NH + h) * DK * DM;
    const int t = threadIdx.x;
    for (int k0 = 0; k0 < DM; k0 += 64) {
        __syncthreads();
        for (int i = 0; i < 16; ++i) {
            int idx = i * 256 + t;
            int r = idx >> 6, c = idx & 63;
            ts[r][c] = W[(size_t)(k0 + r) * DK + c];
        }
        __syncthreads();
        for (int i = 0; i < 16; ++i) {
            int idx = i * 256 + t;
            int n = idx >> 6, c = idx & 63;
            float x = ts[c][n];
            hf h0 = __float2half_rn(x);
            hi[(size_t)n * DM + k0 + c] = h0;
            if (z < 2)
                lo[(size_t)n * DM + k0 + c] =
                    __float2half_rn(x - __half2float(h0));
        }
    }
}

// ---------------------------------------------------------------------------
// GEMM core (R7 config): single 64KB stage, 2 CTAs/SM; co-resident CTA hides
// fill latency. <USE_ALO, USE_BLO>: 3-MMA (t,t) / 2-MMA (f,t) / 1-MMA (f,f).
// ---------------------------------------------------------------------------
#define GEMM_SMEM (65536 + 128)

template <bool USE_ALO, bool USE_BLO>
__device__ __forceinline__ void gemm_fill(uint32_t base,
    const hf* __restrict__ Ahi, const hf* __restrict__ Alo, size_t ar0,
    const hf* __restrict__ Bhi, const hf* __restrict__ Blo, size_t br0,
    int k0)
{
    const int t = threadIdx.x;
    #pragma unroll
    for (int i = 0; i < 4; ++i) {
        int g = i * 256 + t;
        int row = g >> 3, u = g & 7;
        size_t goff = (size_t)row * DM + k0 + u * 8;
        uint32_t s = swz(row, u);
        CP16(base + s, Ahi + (size_t)ar0 * DM + goff);
        if (USE_ALO) CP16(base + 16384 + s, Alo + (size_t)ar0 * DM + goff);
        CP16(base + 32768 + s, Bhi + (size_t)br0 * DM + goff);
        if (USE_BLO) CP16(base + 49152 + s, Blo + (size_t)br0 * DM + goff);
    }
}

template <bool USE_ALO, bool USE_BLO>
__device__ __forceinline__ void gemm_core(uint32_t sb,
    const hf* Ahi, const hf* Alo, size_t ar0,
    const hf* Bhi, const hf* Blo, size_t br0,
    float C[4][4][4])
{
    const int t = threadIdx.x, w = t >> 5, l = t & 31;
    const int wm = (w & 1) * 64, wn = (w >> 1) * 32;
    const int mi = l >> 3;

    gemm_fill<USE_ALO, USE_BLO>(sb, Ahi, Alo, ar0, Bhi, Blo, br0, 0);
    CP_COMMIT();

    for (int c = 0; c < 16; ++c) {
        CP_WAIT0();
        __syncthreads();

        #pragma unroll
        for (int kt = 0; kt < 4; ++kt) {
            uint32_t ahi[4][4], alo[4][4];
            #pragma unroll
            for (int i = 0; i < 4; ++i) {
                int row = wm + 16 * i + (l & 7) + ((mi & 1) << 3);
                int u = kt * 2 + (mi >> 1);
                ldm4(ahi[i], sb + swz(row, u));
                if (USE_ALO) ldm4(alo[i], sb + 16384 + swz(row, u));
            }
            uint32_t bhi[4][2], blo[4][2];
            #pragma unroll
            for (int jp = 0; jp < 2; ++jp) {
                int row = wn + jp * 16 + ((mi >> 1) << 3) + (l & 7);
                int u = kt * 2 + (mi & 1);
                uint32_t r4[4];
                ldm4(r4, sb + 32768 + swz(row, u));
                bhi[2*jp][0] = r4[0]; bhi[2*jp][1] = r4[1];
                bhi[2*jp+1][0] = r4[2]; bhi[2*jp+1][1] = r4[3];
                if (USE_BLO) {
                    ldm4(r4, sb + 49152 + swz(row, u));
                    blo[2*jp][0] = r4[0]; blo[2*jp][1] = r4[1];
                    blo[2*jp+1][0] = r4[2]; blo[2*jp+1][1] = r4[3];
                }
            }
            #pragma unroll
            for (int i = 0; i < 4; ++i)
                #pragma unroll
                for (int j = 0; j < 4; ++j) {
                    mma16816(C[i][j], ahi[i], bhi[j]);
                    if (USE_BLO) mma16816(C[i][j], ahi[i], blo[j]);
                    if (USE_ALO) mma16816(C[i][j], alo[i], bhi[j]);
                }
        }
        __syncthreads();
        if (c + 1 < 16) {
            gemm_fill<USE_ALO, USE_BLO>(sb, Ahi, Alo, ar0, Bhi, Blo, br0,
                                        (c + 1) * 64);
            CP_COMMIT();
        }
    }
}

// ---------------------------------------------------------------------------
// Kernel: per-head-pair input projections. grid (32, 8, 3), 2 CTAs/SM.
// q/k: 3-MMA (logit path). v: 1-MMA (hi x hi).
// ---------------------------------------------------------------------------
__global__ __launch_bounds__(256, 2) void gemm_proj_mma()
{
    extern __shared__ char smraw[];
    uint32_t sb = (smem_u32(smraw) + 127) & ~127u;
    const int z = blockIdx.z, hp = blockIdx.y;
    const size_t row0 = (size_t)blockIdx.x * 128;

    float C[4][4][4] = {};
    const hf* Bhi = g_wthi + (size_t)(z * NH + 2 * hp) * DK * DM;
    const hf* Blo = g_wtlo + (size_t)(z * NH + 2 * hp) * DK * DM;
    if (z < 2)
        gemm_core<true,  true >(sb, g_xhi[z], g_xlo[z], row0, Bhi, Blo, 0, C);
    else
        gemm_core<false, false>(sb, g_xhi[z], nullptr,  row0, Bhi, nullptr, 0, C);

    const int t = threadIdx.x, w = t >> 5, l = t & 31;
    const int gid = l >> 2, tig = l & 3;
    const int wm = (w & 1) * 64, wn = (w >> 1) * 32;

    #pragma unroll
    for (int i = 0; i < 4; ++i)
        #pragma unroll
        for (int j = 0; j < 4; ++j) {
            const int col = wn + 8 * j + 2 * tig;
            const int head = 2 * hp + (col >> 6), d = col & 63;
            const size_t r0 = row0 + wm + 16 * i + gid, r1 = r0 + 8;
            const size_t b = r0 >> 11;
            const size_t hb = (size_t)head * BB + b;
            if (z == 2) {
                const size_t lq0 = r0 & 2047, lq1 = r1 & 2047;
                hf* V = g_vthi + hb * (size_t)DK * LL;
                V[(size_t)d * LL + lq0]       = __float2half_rn(C[i][j][0]);
                V[(size_t)(d + 1) * LL + lq0] = __float2half_rn(C[i][j][1]);
                V[(size_t)d * LL + lq1]       = __float2half_rn(C[i][j][2]);
                V[(size_t)(d + 1) * LL + lq1] = __float2half_rn(C[i][j][3]);
            } else {
                hf* Hi = (z == 0 ? g_qhi : g_khi);
                hf* Lo = (z == 0 ? g_qlo : g_klo);
                #pragma unroll
                for (int rr = 0; rr < 2; ++rr) {
                    const size_t r = rr ? r1 : r0;
                    const float f0 = C[i][j][2 * rr], f1 = C[i][j][2 * rr + 1];
                    uint32_t hh = pack_hf(f0, f1);
                    __half2 h2 = *(__half2*)&hh;
                    uint32_t ll = pack_hf(f0 - __half2float(h2.x),
                                          f1 - __half2float(h2.y));
                    const size_t o = (hb * LL + (r & 2047)) * DK + d;
                    *(uint32_t*)(Hi + o) = hh;
                    *(uint32_t*)(Lo + o) = ll;
                }
            }
        }
}

// ---------------------------------------------------------------------------
// Kernel: output projection + bias. grid (32, 8). 1-MMA, 2 CTAs/SM.
// ---------------------------------------------------------------------------
__global__ __launch_bounds__(256, 2) void gemm_out_mma(
    const float* __restrict__ bias, float* __restrict__ out)
{
    extern __shared__ char smraw[];
    uint32_t sb = (smem_u32(smraw) + 127) & ~127u;
    const size_t row0 = (size_t)blockIdx.x * 128;
    const size_t col0 = (size_t)blockIdx.y * 128;

    float C[4][4][4] = {};
    gemm_core<false, false>(sb, g_atthi, nullptr, row0, g_wphi, nullptr, col0, C);

    const int t = threadIdx.x, w = t >> 5, l = t & 31;
    const int gid = l >> 2, tig = l & 3;
    const int wm = (w & 1) * 64, wn = (w >> 1) * 32;

    #pragma unroll
    for (int i = 0; i < 4; ++i)
        #pragma unroll
        for (int j = 0; j < 4; ++j) {
            size_t col = col0 + wn + 8 * j + 2 * tig;
            size_t r = row0 + wm + 16 * i + gid;
            float2 b2 = *(const float2*)(bias + col);
            *(float2*)(out + r * DM + col) =
                make_float2(C[i][j][0] + b2.x, C[i][j][1] + b2.y);
            *(float2*)(out + (r + 8) * DM + col) =
                make_float2(C[i][j][2] + b2.x, C[i][j][3] + b2.y);
        }
}

// ---------------------------------------------------------------------------
// Flash attention on HMMA (fp16) — unchanged from R13.
// ---------------------------------------------------------------------------
#define ATTN_STAGE 24576
#define ATTN_SMEM (16384 + 4 * ATTN_STAGE + 128)

__device__ __forceinline__ void attn_fill(uint32_t base,
    const hf* khi, const hf* klo, const hf* vthi, int j0)
{
    const int t = threadIdx.x;
    #pragma unroll
    for (int i = 0; i < 2; ++i) {
        int g = i * 256 + t;
        int row = g >> 3, u = g & 7;
        uint32_t s = swz(row, u);
        CP16(base + s,         khi  + (size_t)(j0 + row) * DK + u * 8);
        CP16(base + 8192 + s,  klo  + (size_t)(j0 + row) * DK + u * 8);
        CP16(base + 16384 + s, vthi + (size_t)row * LL + j0 + u * 8);
    }
}

__global__ __launch_bounds__(256, 2) void attn_mma()
{
    extern __shared__ char smraw[];
    const uint32_t sb = (smem_u32(smraw) + 127) & ~127u;
    const uint32_t QLO = sb, ST0 = sb + 16384;

    const int hb = blockIdx.y;
    const int h = hb >> 1, b = hb & 1;
    const int l0 = blockIdx.x * 128;
    const hf* qhi = g_qhi + (size_t)hb * LL * DK;
    const hf* qlo = g_qlo + (size_t)hb * LL * DK;
    const hf* khi = g_khi + (size_t)hb * LL * DK;
    const hf* klo = g_klo + (size_t)hb * LL * DK;
    const hf* vthi = g_vthi + (size_t)hb * DK * LL;

    const int t = threadIdx.x, w = t >> 5, l = t & 31;
    const int gid = l >> 2, tig = l & 3;
    const int mi = l >> 3;

    #pragma unroll
    for (int i = 0; i < 4; ++i) {
        int g = i * 256 + t;
        int row = g >> 3, u = g & 7;
        uint32_t s = swz(row, u);
        *(uint4*)(smraw + (ST0 - sb) + s) =
            *(const uint4*)(qhi + (size_t)(l0 + row) * DK + u * 8);
        *(uint4*)(smraw + (QLO - sb) + s) =
            *(const uint4*)(qlo + (size_t)(l0 + row) * DK + u * 8);
    }
    __syncthreads();

    uint32_t qfh[4][4];
    #pragma unroll
    for (int kt = 0; kt < 4; ++kt) {
        int row = w * 16 + (l & 7) + ((mi & 1) << 3);
        int u = kt * 2 + (mi >> 1);
        ldm4(qfh[kt], ST0 + swz(row, u));
    }
    __syncthreads();

    attn_fill(ST0, khi, klo, vthi, 0);
    CP_COMMIT();
    attn_fill(ST0 + ATTN_STAGE, khi, klo, vthi, 64);
    CP_COMMIT();

    const uint32_t ones2[2] = { 0x3C003C00u, 0x3C003C00u };
    const float L2E = 1.4426950408889634f;

    float o[8][4] = {};
    float osum[4] = {};
    float m0 = -1e30f, m1 = -1e30f;

    for (int jt = 0; jt < 32; ++jt) {
        if (jt + 2 < 32) {
            attn_fill(ST0 + ((jt + 2) & 3) * ATTN_STAGE, khi, klo, vthi,
                      (jt + 2) * 64);
            CP_COMMIT();
            CP_WAIT2();
        } else if (jt + 1 < 32) {
            CP_WAIT1();
        } else {
            CP_WAIT0();
        }
        __syncthreads();
        const uint32_t tb = ST0 + (jt & 3) * ATTN_STAGE;

        float s[8][4] = {};
        #pragma unroll
        for (int kt = 0; kt < 4; ++kt) {
            uint32_t qfl[4];
            {
                int row = w * 16 + (l & 7) + ((mi & 1) << 3);
                int u = kt * 2 + (mi >> 1);
                ldm4(qfl, QLO + swz(row, u));
            }
            uint32_t kh[8][2], kl[8][2];
            #pragma unroll
            for (int jp = 0; jp < 4; ++jp) {
                int row = jp * 16 + ((mi >> 1) << 3) + (l & 7);
                int u = kt * 2 + (mi & 1);
                uint32_t r4[4];
                ldm4(r4, tb + swz(row, u));
                kh[2*jp][0] = r4[0]; kh[2*jp][1] = r4[1];
                kh[2*jp+1][0] = r4[2]; kh[2*jp+1][1] = r4[3];
                ldm4(r4, tb + 8192 + swz(row, u));
                kl[2*jp][0] = r4[0]; kl[2*jp][1] = r4[1];
                kl[2*jp+1][0] = r4[2]; kl[2*jp+1][1] = r4[3];
            }
            #pragma unroll
            for (int n = 0; n < 8; ++n) {
                mma16816(s[n], qfh[kt], kh[n]);
                mma16816(s[n], qfh[kt], kl[n]);
                mma16816(s[n], qfl,     kh[n]);
            }
        }

        float rm0 = -1e30f, rm1 = -1e30f;
        #pragma unroll
        for (int n = 0; n < 8; ++n) {
            rm0 = fmaxf(rm0, fmaxf(s[n][0], s[n][1]));
            rm1 = fmaxf(rm1, fmaxf(s[n][2], s[n][3]));
        }
        rm0 = fmaxf(rm0, __shfl_xor_sync(0xffffffffu, rm0, 1));
        rm0 = fmaxf(rm0, __shfl_xor_sync(0xffffffffu, rm0, 2));
        rm1 = fmaxf(rm1, __shfl_xor_sync(0xffffffffu, rm1, 1));
        rm1 = fmaxf(rm1, __shfl_xor_sync(0xffffffffu, rm1, 2));
        const float mn0 = fmaxf(m0, rm0), mn1 = fmaxf(m1, rm1);
        const float sc0 = __expf(m0 - mn0), sc1 = __expf(m1 - mn1);
        m0 = mn0; m1 = mn1;
        const float mn0L = mn0 * L2E, mn1L = mn1 * L2E;

        uint32_t pp[8][2];
        #pragma unroll
        for (int n = 0; n < 8; ++n) {
            pp[n][0] = ex2_f16x2(pack_hf(fmaf(s[n][0], L2E, -mn0L),
                                         fmaf(s[n][1], L2E, -mn0L)));
            pp[n][1] = ex2_f16x2(pack_hf(fmaf(s[n][2], L2E, -mn1L),
                                         fmaf(s[n][3], L2E, -mn1L)));
        }
        #pragma unroll
        for (int n = 0; n < 8; ++n) {
            o[n][0] *= sc0; o[n][1] *= sc0;
            o[n][2] *= sc1; o[n][3] *= sc1;
        }
        osum[0] *= sc0; osum[1] *= sc0;
        osum[2] *= sc1; osum[3] *= sc1;

        #pragma unroll
        for (int kt = 0; kt < 4; ++kt) {
            uint32_t pah[4] = { pp[2*kt][0], pp[2*kt][1],
                                pp[2*kt+1][0], pp[2*kt+1][1] };
            mma16816(osum, pah, ones2);
            uint32_t vh[8][2];
            #pragma unroll
            for (int jp = 0; jp < 4; ++jp) {
                int row = jp * 16 + ((mi >> 1) << 3) + (l & 7);
                int u = kt * 2 + (mi & 1);
                uint32_t r4[4];
                ldm4(r4, tb + 16384 + swz(row, u));
                vh[2*jp][0] = r4[0]; vh[2*jp][1] = r4[1];
                vh[2*jp+1][0] = r4[2]; vh[2*jp+1][1] = r4[3];
            }
            #pragma unroll
            for (int n = 0; n < 8; ++n)
                mma16816(o[n], pah, vh[n]);
        }
    }

    const float inv0 = 1.0f / osum[0], inv1 = 1.0f / osum[2];
    const size_t r0 = l0 + w * 16 + gid, r1 = r0 + 8;
    #pragma unroll
    for (int n = 0; n < 8; ++n) {
        const int d = 8 * n + 2 * tig;
        __half2 qh2a = *(const __half2*)(qhi + r0 * DK + d);
        __half2 ql2a = *(const __half2*)(qlo + r0 * DK + d);
        __half2 qh2b = *(const __half2*)(qhi + r1 * DK + d);
        __half2 ql2b = *(const __half2*)(qlo + r1 * DK + d);
        float qa0 = __half2float(qh2a.x) + __half2float(ql2a.x);
        float qa1 = __half2float(qh2a.y) + __half2float(ql2a.y);
        float qb0 = __half2float(qh2b.x) + __half2float(ql2b.x);
        float qb1 = __half2float(qh2b.y) + __half2float(ql2b.y);
        float v00 = o[n][0] * inv0 * qa0, v01 = o[n][1] * inv0 * qa1;
        float v10 = o[n][2] * inv1 * qb0, v11 = o[n][3] * inv1 * qb1;

        size_t o0 = ((size_t)b * LL + r0) * DM + h * DK + d;
        size_t o1 = ((size_t)b * LL + r1) * DM + h * DK + d;
        *(uint32_t*)(g_atthi + o0) = pack_hf(v00, v01);
        *(uint32_t*)(g_atthi + o1) = pack_hf(v10, v11);
    }
}

// ---------------------------------------------------------------------------
extern "C" void kernel_launch(void* const* d_in, const int* in_sizes, int n_in,
                              void* d_out, int out_size)
{
    const float* q  = (const float*)d_in[0];
    const float* k  = (const float*)d_in[1];
    const float* v  = (const float*)d_in[2];
    const float* wq = (const float*)d_in[3];
    const float* wk = (const float*)d_in[4];
    const float* wv = (const float*)d_in[5];
    const float* wp = (const float*)d_in[6];
    const float* bp = (const float*)d_in[7];
    float* out = (float*)d_out;

    cudaFuncSetAttribute(gemm_proj_mma,
                         cudaFuncAttributeMaxDynamicSharedMemorySize, GEMM_SMEM);
    cudaFuncSetAttribute(gemm_out_mma,
                         cudaFuncAttributeMaxDynamicSharedMemorySize, GEMM_SMEM);
    cudaFuncSetAttribute(attn_mma,
                         cudaFuncAttributeMaxDynamicSharedMemorySize, ATTN_SMEM);

    const int n4x = MROWS * DM / 4;
    conv_split_kernel<<<dim3((n4x + 255) / 256, 4), 256>>>(q, k, v, wp);
    conv_wt_kernel<<<dim3(NH, 3), 256>>>(wq, wk, wv);

    gemm_proj_mma<<<dim3(MROWS / 128, NH / 2, 3), 256, GEMM_SMEM>>>();

    attn_mma<<<dim3(LL / 128, NH * BB), 256, ATTN_SMEM>>>();

    gemm_out_mma<<<dim3(MROWS / 128, DM / 128), 256, GEMM_SMEM>>>(bp, out);
}

// round 15
// speedup vs baseline: 1.1299x; 1.0054x over previous
#include <cuda_runtime.h>
#include <cuda_fp16.h>
#include <cstdint>

#define BB 2
#define LL 2048
#define DM 1024
#define NH 16
#define DK 64
#define MROWS (BB * LL)   // 4096

typedef __half hf;

// ---------------------------------------------------------------------------
// Global scratch (no allocations allowed)
// ---------------------------------------------------------------------------
__device__ hf g_xhi[3][MROWS * DM];             // split inputs q,k,v (v: hi only)
__device__ hf g_xlo[3][MROWS * DM];
__device__ hf g_wthi[3 * NH * DK * DM];         // W transposed [z][h][n][k]
__device__ hf g_wtlo[3 * NH * DK * DM];
__device__ hf g_wphi[DM * DM];                  // w_proj [n][k] (hi only)

__device__ hf g_qhi[NH * BB * LL * DK];         // [hb][l][k]
__device__ hf g_qlo[NH * BB * LL * DK];
__device__ hf g_khi[NH * BB * LL * DK];
__device__ hf g_klo[NH * BB * LL * DK];
__device__ hf g_vthi[NH * BB * DK * LL];        // [hb][d][l]  (V transposed, hi only)

__device__ hf g_atthi[MROWS * DM];              // attention output (hi only)

// ---------------------------------------------------------------------------
// PTX helpers (base-ISA: mma.sync / ldmatrix / cp.async)
// ---------------------------------------------------------------------------
__device__ __forceinline__ uint32_t smem_u32(const void* p) {
    uint32_t a;
    asm("{ .reg .u64 t; cvta.to.shared.u64 t, %1; cvt.u32.u64 %0, t; }"
        : "=r"(a) : "l"(p));
    return a;
}
__device__ __forceinline__ void ldm4(uint32_t r[4], uint32_t a) {
    asm volatile("ldmatrix.sync.aligned.m8n8.x4.shared.b16 {%0,%1,%2,%3}, [%4];"
        : "=r"(r[0]), "=r"(r[1]), "=r"(r[2]), "=r"(r[3]) : "r"(a));
}
__device__ __forceinline__ void mma16816(float c[4], const uint32_t a[4],
                                         const uint32_t b[2]) {
    asm volatile("mma.sync.aligned.m16n8k16.row.col.f32.f16.f16.f32 "
        "{%0,%1,%2,%3}, {%4,%5,%6,%7}, {%8,%9}, {%0,%1,%2,%3};"
        : "+f"(c[0]), "+f"(c[1]), "+f"(c[2]), "+f"(c[3])
        : "r"(a[0]), "r"(a[1]), "r"(a[2]), "r"(a[3]), "r"(b[0]), "r"(b[1]));
}
#define CP16(dst, src) \
    asm volatile("cp.async.cg.shared.global [%0], [%1], 16;" \
                 :: "r"(dst), "l"(src) : "memory")
#define CP_COMMIT() asm volatile("cp.async.commit_group;" ::: "memory")
#define CP_WAIT2()  asm volatile("cp.async.wait_group 2;" ::: "memory")
#define CP_WAIT1()  asm volatile("cp.async.wait_group 1;" ::: "memory")
#define CP_WAIT0()  asm volatile("cp.async.wait_group 0;" ::: "memory")

// 128B-row tile swizzle: unit = 16B column, XOR by row&7 (conflict-free ldmatrix)
__device__ __forceinline__ uint32_t swz(int row, int u) {
    return (uint32_t)(row * 128 + ((u ^ (row & 7)) << 4));
}
// pack two fp32 into f16x2 (first arg -> low half)
__device__ __forceinline__ uint32_t pack_hf(float lo, float hi) {
    uint32_t r;
    asm("cvt.rn.f16x2.f32 %0, %1, %2;" : "=r"(r) : "f"(hi), "f"(lo));
    return r;
}
// packed fp16x2 exp2
__device__ __forceinline__ uint32_t ex2_f16x2(uint32_t x) {
    uint32_t r;
    asm("ex2.approx.f16x2 %0, %1;" : "=r"(r) : "r"(x));
    return r;
}

// ---------------------------------------------------------------------------
// Conversion kernels
// ---------------------------------------------------------------------------
__global__ void conv_split_kernel(const float* __restrict__ q,
                                  const float* __restrict__ k,
                                  const float* __restrict__ v,
                                  const float* __restrict__ wp)
{
    const int sel = blockIdx.y;
    const float* src;
    hf *hi, *lo;
    bool wlo = true;
    int n4;
    if      (sel == 0) { src = q;  hi = g_xhi[0]; lo = g_xlo[0]; n4 = MROWS * DM / 4; }
    else if (sel == 1) { src = k;  hi = g_xhi[1]; lo = g_xlo[1]; n4 = MROWS * DM / 4; }
    else if (sel == 2) { src = v;  hi = g_xhi[2]; lo = nullptr;  n4 = MROWS * DM / 4; wlo = false; }
    else               { src = wp; hi = g_wphi;   lo = nullptr;  n4 = DM * DM / 4;    wlo = false; }

    int i = blockIdx.x * 256 + threadIdx.x;
    if (i >= n4) return;
    float4 vv = ((const float4*)src)[i];
    uint32_t h01 = pack_hf(vv.x, vv.y);
    uint32_t h23 = pack_hf(vv.z, vv.w);
    ((uint32_t*)hi)[2 * i]     = h01;
    ((uint32_t*)hi)[2 * i + 1] = h23;
    if (wlo) {
        __half2 f01 = *(__half2*)&h01, f23 = *(__half2*)&h23;
        ((uint32_t*)lo)[2 * i] =
            pack_hf(vv.x - __half2float(f01.x), vv.y - __half2float(f01.y));
        ((uint32_t*)lo)[2 * i + 1] =
            pack_hf(vv.z - __half2float(f23.x), vv.w - __half2float(f23.y));
    }
}

__global__ void conv_wt_kernel(const float* __restrict__ wq,
                               const float* __restrict__ wk,
                               const float* __restrict__ wv)
{
    __shared__ float ts[64][65];
    const int h = blockIdx.x, z = blockIdx.y;
    const float* W = (z == 0 ? wq : z == 1 ? wk : wv) + (size_t)h * DM * DK;
    hf* hi = g_wthi + (size_t)(z * NH + h) * DK * DM;
    hf* lo = g_wtlo + (size_t)(z * NH + h) * DK * DM;
    const int t = threadIdx.x;
    for (int k0 = 0; k0 < DM; k0 += 64) {
        __syncthreads();
        for (int i = 0; i < 16; ++i) {
            int idx = i * 256 + t;
            int r = idx >> 6, c = idx & 63;
            ts[r][c] = W[(size_t)(k0 + r) * DK + c];
        }
        __syncthreads();
        for (int i = 0; i < 16; ++i) {
            int idx = i * 256 + t;
            int n = idx >> 6, c = idx & 63;
            float x = ts[c][n];
            hf h0 = __float2half_rn(x);
            hi[(size_t)n * DM + k0 + c] = h0;
            if (z < 2)
                lo[(size_t)n * DM + k0 + c] =
                    __float2half_rn(x - __half2float(h0));
        }
    }
}

// ---------------------------------------------------------------------------
// GEMM core (R7 config): single 64KB stage, 2 CTAs/SM; co-resident CTA hides
// fill latency. <USE_ALO, USE_BLO>: 3-MMA (t,t) / 2-MMA (f,t) / 1-MMA (f,f).
// ---------------------------------------------------------------------------
#define GEMM_SMEM (65536 + 128)

template <bool USE_ALO, bool USE_BLO>
__device__ __forceinline__ void gemm_fill(uint32_t base,
    const hf* __restrict__ Ahi, const hf* __restrict__ Alo, size_t ar0,
    const hf* __restrict__ Bhi, const hf* __restrict__ Blo, size_t br0,
    int k0)
{
    const int t = threadIdx.x;
    #pragma unroll
    for (int i = 0; i < 4; ++i) {
        int g = i * 256 + t;
        int row = g >> 3, u = g & 7;
        size_t goff = (size_t)row * DM + k0 + u * 8;
        uint32_t s = swz(row, u);
        CP16(base + s, Ahi + (size_t)ar0 * DM + goff);
        if (USE_ALO) CP16(base + 16384 + s, Alo + (size_t)ar0 * DM + goff);
        CP16(base + 32768 + s, Bhi + (size_t)br0 * DM + goff);
        if (USE_BLO) CP16(base + 49152 + s, Blo + (size_t)br0 * DM + goff);
    }
}

template <bool USE_ALO, bool USE_BLO>
__device__ __forceinline__ void gemm_core(uint32_t sb,
    const hf* Ahi, const hf* Alo, size_t ar0,
    const hf* Bhi, const hf* Blo, size_t br0,
    float C[4][4][4])
{
    const int t = threadIdx.x, w = t >> 5, l = t & 31;
    const int wm = (w & 1) * 64, wn = (w >> 1) * 32;
    const int mi = l >> 3;

    gemm_fill<USE_ALO, USE_BLO>(sb, Ahi, Alo, ar0, Bhi, Blo, br0, 0);
    CP_COMMIT();

    for (int c = 0; c < 16; ++c) {
        CP_WAIT0();
        __syncthreads();

        #pragma unroll
        for (int kt = 0; kt < 4; ++kt) {
            uint32_t ahi[4][4], alo[4][4];
            #pragma unroll
            for (int i = 0; i < 4; ++i) {
                int row = wm + 16 * i + (l & 7) + ((mi & 1) << 3);
                int u = kt * 2 + (mi >> 1);
                ldm4(ahi[i], sb + swz(row, u));
                if (USE_ALO) ldm4(alo[i], sb + 16384 + swz(row, u));
            }
            uint32_t bhi[4][2], blo[4][2];
            #pragma unroll
            for (int jp = 0; jp < 2; ++jp) {
                int row = wn + jp * 16 + ((mi >> 1) << 3) + (l & 7);
                int u = kt * 2 + (mi & 1);
                uint32_t r4[4];
                ldm4(r4, sb + 32768 + swz(row, u));
                bhi[2*jp][0] = r4[0]; bhi[2*jp][1] = r4[1];
                bhi[2*jp+1][0] = r4[2]; bhi[2*jp+1][1] = r4[3];
                if (USE_BLO) {
                    ldm4(r4, sb + 49152 + swz(row, u));
                    blo[2*jp][0] = r4[0]; blo[2*jp][1] = r4[1];
                    blo[2*jp+1][0] = r4[2]; blo[2*jp+1][1] = r4[3];
                }
            }
            #pragma unroll
            for (int i = 0; i < 4; ++i)
                #pragma unroll
                for (int j = 0; j < 4; ++j) {
                    mma16816(C[i][j], ahi[i], bhi[j]);
                    if (USE_BLO) mma16816(C[i][j], ahi[i], blo[j]);
                    if (USE_ALO) mma16816(C[i][j], alo[i], bhi[j]);
                }
        }
        __syncthreads();
        if (c + 1 < 16) {
            gemm_fill<USE_ALO, USE_BLO>(sb, Ahi, Alo, ar0, Bhi, Blo, br0,
                                        (c + 1) * 64);
            CP_COMMIT();
        }
    }
}

// ---------------------------------------------------------------------------
// Kernel: per-head-pair input projections. grid (32, 8, 3), 2 CTAs/SM.
// q/k: 3-MMA (logit path). v: 1-MMA (hi x hi).
// ---------------------------------------------------------------------------
__global__ __launch_bounds__(256, 2) void gemm_proj_mma()
{
    extern __shared__ char smraw[];
    uint32_t sb = (smem_u32(smraw) + 127) & ~127u;
    const int z = blockIdx.z, hp = blockIdx.y;
    const size_t row0 = (size_t)blockIdx.x * 128;

    float C[4][4][4] = {};
    const hf* Bhi = g_wthi + (size_t)(z * NH + 2 * hp) * DK * DM;
    const hf* Blo = g_wtlo + (size_t)(z * NH + 2 * hp) * DK * DM;
    if (z < 2)
        gemm_core<true,  true >(sb, g_xhi[z], g_xlo[z], row0, Bhi, Blo, 0, C);
    else
        gemm_core<false, false>(sb, g_xhi[z], nullptr,  row0, Bhi, nullptr, 0, C);

    const int t = threadIdx.x, w = t >> 5, l = t & 31;
    const int gid = l >> 2, tig = l & 3;
    const int wm = (w & 1) * 64, wn = (w >> 1) * 32;

    #pragma unroll
    for (int i = 0; i < 4; ++i)
        #pragma unroll
        for (int j = 0; j < 4; ++j) {
            const int col = wn + 8 * j + 2 * tig;
            const int head = 2 * hp + (col >> 6), d = col & 63;
            const size_t r0 = row0 + wm + 16 * i + gid, r1 = r0 + 8;
            const size_t b = r0 >> 11;
            const size_t hb = (size_t)head * BB + b;
            if (z == 2) {
                const size_t lq0 = r0 & 2047, lq1 = r1 & 2047;
                hf* V = g_vthi + hb * (size_t)DK * LL;
                V[(size_t)d * LL + lq0]       = __float2half_rn(C[i][j][0]);
                V[(size_t)(d + 1) * LL + lq0] = __float2half_rn(C[i][j][1]);
                V[(size_t)d * LL + lq1]       = __float2half_rn(C[i][j][2]);
                V[(size_t)(d + 1) * LL + lq1] = __float2half_rn(C[i][j][3]);
            } else {
                hf* Hi = (z == 0 ? g_qhi : g_khi);
                hf* Lo = (z == 0 ? g_qlo : g_klo);
                #pragma unroll
                for (int rr = 0; rr < 2; ++rr) {
                    const size_t r = rr ? r1 : r0;
                    const float f0 = C[i][j][2 * rr], f1 = C[i][j][2 * rr + 1];
                    uint32_t hh = pack_hf(f0, f1);
                    __half2 h2 = *(__half2*)&hh;
                    uint32_t ll = pack_hf(f0 - __half2float(h2.x),
                                          f1 - __half2float(h2.y));
                    const size_t o = (hb * LL + (r & 2047)) * DK + d;
                    *(uint32_t*)(Hi + o) = hh;
                    *(uint32_t*)(Lo + o) = ll;
                }
            }
        }
}

// ---------------------------------------------------------------------------
// Kernel: output projection + bias. grid (32, 8). 1-MMA, 2 CTAs/SM.
// ---------------------------------------------------------------------------
__global__ __launch_bounds__(256, 2) void gemm_out_mma(
    const float* __restrict__ bias, float* __restrict__ out)
{
    extern __shared__ char smraw[];
    uint32_t sb = (smem_u32(smraw) + 127) & ~127u;
    const size_t row0 = (size_t)blockIdx.x * 128;
    const size_t col0 = (size_t)blockIdx.y * 128;

    float C[4][4][4] = {};
    gemm_core<false, false>(sb, g_atthi, nullptr, row0, g_wphi, nullptr, col0, C);

    const int t = threadIdx.x, w = t >> 5, l = t & 31;
    const int gid = l >> 2, tig = l & 3;
    const int wm = (w & 1) * 64, wn = (w >> 1) * 32;

    #pragma unroll
    for (int i = 0; i < 4; ++i)
        #pragma unroll
        for (int j = 0; j < 4; ++j) {
            size_t col = col0 + wn + 8 * j + 2 * tig;
            size_t r = row0 + wm + 16 * i + gid;
            float2 b2 = *(const float2*)(bias + col);
            *(float2*)(out + r * DM + col) =
                make_float2(C[i][j][0] + b2.x, C[i][j][1] + b2.y);
            *(float2*)(out + (r + 8) * DM + col) =
                make_float2(C[i][j][2] + b2.x, C[i][j][3] + b2.y);
        }
}

// ---------------------------------------------------------------------------
// Flash attention on HMMA (fp16) — unchanged from R13.
// ---------------------------------------------------------------------------
#define ATTN_STAGE 24576
#define ATTN_SMEM (16384 + 4 * ATTN_STAGE + 128)

__device__ __forceinline__ void attn_fill(uint32_t base,
    const hf* khi, const hf* klo, const hf* vthi, int j0)
{
    const int t = threadIdx.x;
    #pragma unroll
    for (int i = 0; i < 2; ++i) {
        int g = i * 256 + t;
        int row = g >> 3, u = g & 7;
        uint32_t s = swz(row, u);
        CP16(base + s,         khi  + (size_t)(j0 + row) * DK + u * 8);
        CP16(base + 8192 + s,  klo  + (size_t)(j0 + row) * DK + u * 8);
        CP16(base + 16384 + s, vthi + (size_t)row * LL + j0 + u * 8);
    }
}

__global__ __launch_bounds__(256, 2) void attn_mma()
{
    extern __shared__ char smraw[];
    const uint32_t sb = (smem_u32(smraw) + 127) & ~127u;
    const uint32_t QLO = sb, ST0 = sb + 16384;

    const int hb = blockIdx.y;
    const int h = hb >> 1, b = hb & 1;
    const int l0 = blockIdx.x * 128;
    const hf* qhi = g_qhi + (size_t)hb * LL * DK;
    const hf* qlo = g_qlo + (size_t)hb * LL * DK;
    const hf* khi = g_khi + (size_t)hb * LL * DK;
    const hf* klo = g_klo + (size_t)hb * LL * DK;
    const hf* vthi = g_vthi + (size_t)hb * DK * LL;

    const int t = threadIdx.x, w = t >> 5, l = t & 31;
    const int gid = l >> 2, tig = l & 3;
    const int mi = l >> 3;

    #pragma unroll
    for (int i = 0; i < 4; ++i) {
        int g = i * 256 + t;
        int row = g >> 3, u = g & 7;
        uint32_t s = swz(row, u);
        *(uint4*)(smraw + (ST0 - sb) + s) =
            *(const uint4*)(qhi + (size_t)(l0 + row) * DK + u * 8);
        *(uint4*)(smraw + (QLO - sb) + s) =
            *(const uint4*)(qlo + (size_t)(l0 + row) * DK + u * 8);
    }
    __syncthreads();

    uint32_t qfh[4][4];
    #pragma unroll
    for (int kt = 0; kt < 4; ++kt) {
        int row = w * 16 + (l & 7) + ((mi & 1) << 3);
        int u = kt * 2 + (mi >> 1);
        ldm4(qfh[kt], ST0 + swz(row, u));
    }
    __syncthreads();

    attn_fill(ST0, khi, klo, vthi, 0);
    CP_COMMIT();
    attn_fill(ST0 + ATTN_STAGE, khi, klo, vthi, 64);
    CP_COMMIT();

    const uint32_t ones2[2] = { 0x3C003C00u, 0x3C003C00u };
    const float L2E = 1.4426950408889634f;

    float o[8][4] = {};
    float osum[4] = {};
    float m0 = -1e30f, m1 = -1e30f;

    for (int jt = 0; jt < 32; ++jt) {
        if (jt + 2 < 32) {
            attn_fill(ST0 + ((jt + 2) & 3) * ATTN_STAGE, khi, klo, vthi,
                      (jt + 2) * 64);
            CP_COMMIT();
            CP_WAIT2();
        } else if (jt + 1 < 32) {
            CP_WAIT1();
        } else {
            CP_WAIT0();
        }
        __syncthreads();
        const uint32_t tb = ST0 + (jt & 3) * ATTN_STAGE;

        float s[8][4] = {};
        #pragma unroll
        for (int kt = 0; kt < 4; ++kt) {
            uint32_t qfl[4];
            {
                int row = w * 16 + (l & 7) + ((mi & 1) << 3);
                int u = kt * 2 + (mi >> 1);
                ldm4(qfl, QLO + swz(row, u));
            }
            uint32_t kh[8][2], kl[8][2];
            #pragma unroll
            for (int jp = 0; jp < 4; ++jp) {
                int row = jp * 16 + ((mi >> 1) << 3) + (l & 7);
                int u = kt * 2 + (mi & 1);
                uint32_t r4[4];
                ldm4(r4, tb + swz(row, u));
                kh[2*jp][0] = r4[0]; kh[2*jp][1] = r4[1];
                kh[2*jp+1][0] = r4[2]; kh[2*jp+1][1] = r4[3];
                ldm4(r4, tb + 8192 + swz(row, u));
                kl[2*jp][0] = r4[0]; kl[2*jp][1] = r4[1];
                kl[2*jp+1][0] = r4[2]; kl[2*jp+1][1] = r4[3];
            }
            #pragma unroll
            for (int n = 0; n < 8; ++n) {
                mma16816(s[n], qfh[kt], kh[n]);
                mma16816(s[n], qfh[kt], kl[n]);
                mma16816(s[n], qfl,     kh[n]);
            }
        }

        float rm0 = -1e30f, rm1 = -1e30f;
        #pragma unroll
        for (int n = 0; n < 8; ++n) {
            rm0 = fmaxf(rm0, fmaxf(s[n][0], s[n][1]));
            rm1 = fmaxf(rm1, fmaxf(s[n][2], s[n][3]));
        }
        rm0 = fmaxf(rm0, __shfl_xor_sync(0xffffffffu, rm0, 1));
        rm0 = fmaxf(rm0, __shfl_xor_sync(0xffffffffu, rm0, 2));
        rm1 = fmaxf(rm1, __shfl_xor_sync(0xffffffffu, rm1, 1));
        rm1 = fmaxf(rm1, __shfl_xor_sync(0xffffffffu, rm1, 2));
        const float mn0 = fmaxf(m0, rm0), mn1 = fmaxf(m1, rm1);
        const float sc0 = __expf(m0 - mn0), sc1 = __expf(m1 - mn1);
        m0 = mn0; m1 = mn1;
        const float mn0L = mn0 * L2E, mn1L = mn1 * L2E;

        uint32_t pp[8][2];
        #pragma unroll
        for (int n = 0; n < 8; ++n) {
            pp[n][0] = ex2_f16x2(pack_hf(fmaf(s[n][0], L2E, -mn0L),
                                         fmaf(s[n][1], L2E, -mn0L)));
            pp[n][1] = ex2_f16x2(pack_hf(fmaf(s[n][2], L2E, -mn1L),
                                         fmaf(s[n][3], L2E, -mn1L)));
        }
        #pragma unroll
        for (int n = 0; n < 8; ++n) {
            o[n][0] *= sc0; o[n][1] *= sc0;
            o[n][2] *= sc1; o[n][3] *= sc1;
        }
        osum[0] *= sc0; osum[1] *= sc0;
        osum[2] *= sc1; osum[3] *= sc1;

        #pragma unroll
        for (int kt = 0; kt < 4; ++kt) {
            uint32_t pah[4] = { pp[2*kt][0], pp[2*kt][1],
                                pp[2*kt+1][0], pp[2*kt+1][1] };
            mma16816(osum, pah, ones2);
            uint32_t vh[8][2];
            #pragma unroll
            for (int jp = 0; jp < 4; ++jp) {
                int row = jp * 16 + ((mi >> 1) << 3) + (l & 7);
                int u = kt * 2 + (mi & 1);
                uint32_t r4[4];
                ldm4(r4, tb + 16384 + swz(row, u));
                vh[2*jp][0] = r4[0]; vh[2*jp][1] = r4[1];
                vh[2*jp+1][0] = r4[2]; vh[2*jp+1][1] = r4[3];
            }
            #pragma unroll
            for (int n = 0; n < 8; ++n)
                mma16816(o[n], pah, vh[n]);
        }
    }

    const float inv0 = 1.0f / osum[0], inv1 = 1.0f / osum[2];
    const size_t r0 = l0 + w * 16 + gid, r1 = r0 + 8;
    #pragma unroll
    for (int n = 0; n < 8; ++n) {
        const int d = 8 * n + 2 * tig;
        __half2 qh2a = *(const __half2*)(qhi + r0 * DK + d);
        __half2 ql2a = *(const __half2*)(qlo + r0 * DK + d);
        __half2 qh2b = *(const __half2*)(qhi + r1 * DK + d);
        __half2 ql2b = *(const __half2*)(qlo + r1 * DK + d);
        float qa0 = __half2float(qh2a.x) + __half2float(ql2a.x);
        float qa1 = __half2float(qh2a.y) + __half2float(ql2a.y);
        float qb0 = __half2float(qh2b.x) + __half2float(ql2b.x);
        float qb1 = __half2float(qh2b.y) + __half2float(ql2b.y);
        float v00 = o[n][0] * inv0 * qa0, v01 = o[n][1] * inv0 * qa1;
        float v10 = o[n][2] * inv1 * qb0, v11 = o[n][3] * inv1 * qb1;

        size_t o0 = ((size_t)b * LL + r0) * DM + h * DK + d;
        size_t o1 = ((size_t)b * LL + r1) * DM + h * DK + d;
        *(uint32_t*)(g_atthi + o0) = pack_hf(v00, v01);
        *(uint32_t*)(g_atthi + o1) = pack_hf(v10, v11);
    }
}

// ---------------------------------------------------------------------------
extern "C" void kernel_launch(void* const* d_in, const int* in_sizes, int n_in,
                              void* d_out, int out_size)
{
    const float* q  = (const float*)d_in[0];
    const float* k  = (const float*)d_in[1];
    const float* v  = (const float*)d_in[2];
    const float* wq = (const float*)d_in[3];
    const float* wk = (const float*)d_in[4];
    const float* wv = (const float*)d_in[5];
    const float* wp = (const float*)d_in[6];
    const float* bp = (const float*)d_in[7];
    float* out = (float*)d_out;

    cudaFuncSetAttribute(gemm_proj_mma,
                         cudaFuncAttributeMaxDynamicSharedMemorySize, GEMM_SMEM);
    cudaFuncSetAttribute(gemm_out_mma,
                         cudaFuncAttributeMaxDynamicSharedMemorySize, GEMM_SMEM);
    cudaFuncSetAttribute(attn_mma,
                         cudaFuncAttributeMaxDynamicSharedMemorySize, ATTN_SMEM);

    const int n4x = MROWS * DM / 4;
    conv_split_kernel<<<dim3((n4x + 255) / 256, 4), 256>>>(q, k, v, wp);
    conv_wt_kernel<<<dim3(NH, 3), 256>>>(wq, wk, wv);

    gemm_proj_mma<<<dim3(MROWS / 128, NH / 2, 3), 256, GEMM_SMEM>>>();

    attn_mma<<<dim3(LL / 128, NH * BB), 256, ATTN_SMEM>>>();

    gemm_out_mma<<<dim3(MROWS / 128, DM / 128), 256, GEMM_SMEM>>>(bp, out);
}

// round 16
// speedup vs baseline: 1.1337x; 1.0034x over previous
#include <cuda_runtime.h>
#include <cuda_fp16.h>
#include <cstdint>

#define BB 2
#define LL 2048
#define DM 1024
#define NH 16
#define DK 64
#define MROWS (BB * LL)   // 4096

typedef __half hf;

// ---------------------------------------------------------------------------
// Global scratch (no allocations allowed)
// ---------------------------------------------------------------------------
__device__ hf g_xhi[3][MROWS * DM];             // split inputs q,k,v (v: hi only)
__device__ hf g_xlo[3][MROWS * DM];
__device__ hf g_wthi[3 * NH * DK * DM];         // W transposed [z][h][n][k]
__device__ hf g_wtlo[3 * NH * DK * DM];
__device__ hf g_wphi[DM * DM];                  // w_proj [n][k] (hi only)

__device__ hf g_qhi[NH * BB * LL * DK];         // [hb][l][k]
__device__ hf g_qlo[NH * BB * LL * DK];
__device__ hf g_khi[NH * BB * LL * DK];
__device__ hf g_klo[NH * BB * LL * DK];
__device__ hf g_vthi[NH * BB * DK * LL];        // [hb][d][l]  (V transposed, hi only)

__device__ hf g_atthi[MROWS * DM];              // attention output (hi only)

// ---------------------------------------------------------------------------
// PTX helpers (base-ISA: mma.sync / ldmatrix / cp.async)
// ---------------------------------------------------------------------------
__device__ __forceinline__ uint32_t smem_u32(const void* p) {
    uint32_t a;
    asm("{ .reg .u64 t; cvta.to.shared.u64 t, %1; cvt.u32.u64 %0, t; }"
        : "=r"(a) : "l"(p));
    return a;
}
__device__ __forceinline__ void ldm4(uint32_t r[4], uint32_t a) {
    asm volatile("ldmatrix.sync.aligned.m8n8.x4.shared.b16 {%0,%1,%2,%3}, [%4];"
        : "=r"(r[0]), "=r"(r[1]), "=r"(r[2]), "=r"(r[3]) : "r"(a));
}
__device__ __forceinline__ void mma16816(float c[4], const uint32_t a[4],
                                         const uint32_t b[2]) {
    asm volatile("mma.sync.aligned.m16n8k16.row.col.f32.f16.f16.f32 "
        "{%0,%1,%2,%3}, {%4,%5,%6,%7}, {%8,%9}, {%0,%1,%2,%3};"
        : "+f"(c[0]), "+f"(c[1]), "+f"(c[2]), "+f"(c[3])
        : "r"(a[0]), "r"(a[1]), "r"(a[2]), "r"(a[3]), "r"(b[0]), "r"(b[1]));
}
#define CP16(dst, src) \
    asm volatile("cp.async.cg.shared.global [%0], [%1], 16;" \
                 :: "r"(dst), "l"(src) : "memory")
#define CP_COMMIT() asm volatile("cp.async.commit_group;" ::: "memory")
#define CP_WAIT2()  asm volatile("cp.async.wait_group 2;" ::: "memory")
#define CP_WAIT1()  asm volatile("cp.async.wait_group 1;" ::: "memory")
#define CP_WAIT0()  asm volatile("cp.async.wait_group 0;" ::: "memory")

// 128B-row tile swizzle: unit = 16B column, XOR by row&7 (conflict-free ldmatrix)
__device__ __forceinline__ uint32_t swz(int row, int u) {
    return (uint32_t)(row * 128 + ((u ^ (row & 7)) << 4));
}
// pack two fp32 into f16x2 (first arg -> low half)
__device__ __forceinline__ uint32_t pack_hf(float lo, float hi) {
    uint32_t r;
    asm("cvt.rn.f16x2.f32 %0, %1, %2;" : "=r"(r) : "f"(hi), "f"(lo));
    return r;
}
// packed fp16x2 exp2
__device__ __forceinline__ uint32_t ex2_f16x2(uint32_t x) {
    uint32_t r;
    asm("ex2.approx.f16x2 %0, %1;" : "=r"(r) : "r"(x));
    return r;
}

// ---------------------------------------------------------------------------
// Conversion kernels
// ---------------------------------------------------------------------------
__global__ void conv_split_kernel(const float* __restrict__ q,
                                  const float* __restrict__ k,
                                  const float* __restrict__ v,
                                  const float* __restrict__ wp)
{
    const int sel = blockIdx.y;
    const float* src;
    hf *hi, *lo;
    bool wlo = true;
    int n4;
    if      (sel == 0) { src = q;  hi = g_xhi[0]; lo = g_xlo[0]; n4 = MROWS * DM / 4; }
    else if (sel == 1) { src = k;  hi = g_xhi[1]; lo = g_xlo[1]; n4 = MROWS * DM / 4; }
    else if (sel == 2) { src = v;  hi = g_xhi[2]; lo = nullptr;  n4 = MROWS * DM / 4; wlo = false; }
    else               { src = wp; hi = g_wphi;   lo = nullptr;  n4 = DM * DM / 4;    wlo = false; }

    int i = blockIdx.x * 256 + threadIdx.x;
    if (i >= n4) return;
    float4 vv = ((const float4*)src)[i];
    uint32_t h01 = pack_hf(vv.x, vv.y);
    uint32_t h23 = pack_hf(vv.z, vv.w);
    ((uint32_t*)hi)[2 * i]     = h01;
    ((uint32_t*)hi)[2 * i + 1] = h23;
    if (wlo) {
        __half2 f01 = *(__half2*)&h01, f23 = *(__half2*)&h23;
        ((uint32_t*)lo)[2 * i] =
            pack_hf(vv.x - __half2float(f01.x), vv.y - __half2float(f01.y));
        ((uint32_t*)lo)[2 * i + 1] =
            pack_hf(vv.z - __half2float(f23.x), vv.w - __half2float(f23.y));
    }
}

__global__ void conv_wt_kernel(const float* __restrict__ wq,
                               const float* __restrict__ wk,
                               const float* __restrict__ wv)
{
    __shared__ float ts[64][65];
    const int h = blockIdx.x, z = blockIdx.y;
    const float* W = (z == 0 ? wq : z == 1 ? wk : wv) + (size_t)h * DM * DK;
    hf* hi = g_wthi + (size_t)(z * NH + h) * DK * DM;
    hf* lo = g_wtlo + (size_t)(z * NH + h) * DK * DM;
    const int t = threadIdx.x;
    for (int k0 = 0; k0 < DM; k0 += 64) {
        __syncthreads();
        for (int i = 0; i < 16; ++i) {
            int idx = i * 256 + t;
            int r = idx >> 6, c = idx & 63;
            ts[r][c] = W[(size_t)(k0 + r) * DK + c];
        }
        __syncthreads();
        for (int i = 0; i < 16; ++i) {
            int idx = i * 256 + t;
            int n = idx >> 6, c = idx & 63;
            float x = ts[c][n];
            hf h0 = __float2half_rn(x);
            hi[(size_t)n * DM + k0 + c] = h0;
            if (z < 2)
                lo[(size_t)n * DM + k0 + c] =
                    __float2half_rn(x - __half2float(h0));
        }
    }
}

// ---------------------------------------------------------------------------
// GEMM core (R7 config): single 64KB stage, 2 CTAs/SM; co-resident CTA hides
// fill latency. <USE_ALO, USE_BLO>: 3-MMA (t,t) / 2-MMA (f,t) / 1-MMA (f,f).
// ---------------------------------------------------------------------------
#define GEMM_SMEM (65536 + 128)

template <bool USE_ALO, bool USE_BLO>
__device__ __forceinline__ void gemm_fill(uint32_t base,
    const hf* __restrict__ Ahi, const hf* __restrict__ Alo, size_t ar0,
    const hf* __restrict__ Bhi, const hf* __restrict__ Blo, size_t br0,
    int k0)
{
    const int t = threadIdx.x;
    #pragma unroll
    for (int i = 0; i < 4; ++i) {
        int g = i * 256 + t;
        int row = g >> 3, u = g & 7;
        size_t goff = (size_t)row * DM + k0 + u * 8;
        uint32_t s = swz(row, u);
        CP16(base + s, Ahi + (size_t)ar0 * DM + goff);
        if (USE_ALO) CP16(base + 16384 + s, Alo + (size_t)ar0 * DM + goff);
        CP16(base + 32768 + s, Bhi + (size_t)br0 * DM + goff);
        if (USE_BLO) CP16(base + 49152 + s, Blo + (size_t)br0 * DM + goff);
    }
}

template <bool USE_ALO, bool USE_BLO>
__device__ __forceinline__ void gemm_core(uint32_t sb,
    const hf* Ahi, const hf* Alo, size_t ar0,
    const hf* Bhi, const hf* Blo, size_t br0,
    float C[4][4][4])
{
    const int t = threadIdx.x, w = t >> 5, l = t & 31;
    const int wm = (w & 1) * 64, wn = (w >> 1) * 32;
    const int mi = l >> 3;

    gemm_fill<USE_ALO, USE_BLO>(sb, Ahi, Alo, ar0, Bhi, Blo, br0, 0);
    CP_COMMIT();

    for (int c = 0; c < 16; ++c) {
        CP_WAIT0();
        __syncthreads();

        #pragma unroll
        for (int kt = 0; kt < 4; ++kt) {
            uint32_t ahi[4][4], alo[4][4];
            #pragma unroll
            for (int i = 0; i < 4; ++i) {
                int row = wm + 16 * i + (l & 7) + ((mi & 1) << 3);
                int u = kt * 2 + (mi >> 1);
                ldm4(ahi[i], sb + swz(row, u));
                if (USE_ALO) ldm4(alo[i], sb + 16384 + swz(row, u));
            }
            uint32_t bhi[4][2], blo[4][2];
            #pragma unroll
            for (int jp = 0; jp < 2; ++jp) {
                int row = wn + jp * 16 + ((mi >> 1) << 3) + (l & 7);
                int u = kt * 2 + (mi & 1);
                uint32_t r4[4];
                ldm4(r4, sb + 32768 + swz(row, u));
                bhi[2*jp][0] = r4[0]; bhi[2*jp][1] = r4[1];
                bhi[2*jp+1][0] = r4[2]; bhi[2*jp+1][1] = r4[3];
                if (USE_BLO) {
                    ldm4(r4, sb + 49152 + swz(row, u));
                    blo[2*jp][0] = r4[0]; blo[2*jp][1] = r4[1];
                    blo[2*jp+1][0] = r4[2]; blo[2*jp+1][1] = r4[3];
                }
            }
            #pragma unroll
            for (int i = 0; i < 4; ++i)
                #pragma unroll
                for (int j = 0; j < 4; ++j) {
                    mma16816(C[i][j], ahi[i], bhi[j]);
                    if (USE_BLO) mma16816(C[i][j], ahi[i], blo[j]);
                    if (USE_ALO) mma16816(C[i][j], alo[i], bhi[j]);
                }
        }
        __syncthreads();
        if (c + 1 < 16) {
            gemm_fill<USE_ALO, USE_BLO>(sb, Ahi, Alo, ar0, Bhi, Blo, br0,
                                        (c + 1) * 64);
            CP_COMMIT();
        }
    }
}

// ---------------------------------------------------------------------------
// Kernel: per-head-pair input projections. grid (32, 8, 3), 2 CTAs/SM.
// q/k: 3-MMA (logit path). v: 1-MMA (hi x hi).
// ---------------------------------------------------------------------------
__global__ __launch_bounds__(256, 2) void gemm_proj_mma()
{
    extern __shared__ char smraw[];
    uint32_t sb = (smem_u32(smraw) + 127) & ~127u;
    const int z = blockIdx.z, hp = blockIdx.y;
    const size_t row0 = (size_t)blockIdx.x * 128;

    float C[4][4][4] = {};
    const hf* Bhi = g_wthi + (size_t)(z * NH + 2 * hp) * DK * DM;
    const hf* Blo = g_wtlo + (size_t)(z * NH + 2 * hp) * DK * DM;
    if (z < 2)
        gemm_core<true,  true >(sb, g_xhi[z], g_xlo[z], row0, Bhi, Blo, 0, C);
    else
        gemm_core<false, false>(sb, g_xhi[z], nullptr,  row0, Bhi, nullptr, 0, C);

    const int t = threadIdx.x, w = t >> 5, l = t & 31;
    const int gid = l >> 2, tig = l & 3;
    const int wm = (w & 1) * 64, wn = (w >> 1) * 32;

    #pragma unroll
    for (int i = 0; i < 4; ++i)
        #pragma unroll
        for (int j = 0; j < 4; ++j) {
            const int col = wn + 8 * j + 2 * tig;
            const int head = 2 * hp + (col >> 6), d = col & 63;
            const size_t r0 = row0 + wm + 16 * i + gid, r1 = r0 + 8;
            const size_t b = r0 >> 11;
            const size_t hb = (size_t)head * BB + b;
            if (z == 2) {
                const size_t lq0 = r0 & 2047, lq1 = r1 & 2047;
                hf* V = g_vthi + hb * (size_t)DK * LL;
                V[(size_t)d * LL + lq0]       = __float2half_rn(C[i][j][0]);
                V[(size_t)(d + 1) * LL + lq0] = __float2half_rn(C[i][j][1]);
                V[(size_t)d * LL + lq1]       = __float2half_rn(C[i][j][2]);
                V[(size_t)(d + 1) * LL + lq1] = __float2half_rn(C[i][j][3]);
            } else {
                hf* Hi = (z == 0 ? g_qhi : g_khi);
                hf* Lo = (z == 0 ? g_qlo : g_klo);
                #pragma unroll
                for (int rr = 0; rr < 2; ++rr) {
                    const size_t r = rr ? r1 : r0;
                    const float f0 = C[i][j][2 * rr], f1 = C[i][j][2 * rr + 1];
                    uint32_t hh = pack_hf(f0, f1);
                    __half2 h2 = *(__half2*)&hh;
                    uint32_t ll = pack_hf(f0 - __half2float(h2.x),
                                          f1 - __half2float(h2.y));
                    const size_t o = (hb * LL + (r & 2047)) * DK + d;
                    *(uint32_t*)(Hi + o) = hh;
                    *(uint32_t*)(Lo + o) = ll;
                }
            }
        }
}

// ---------------------------------------------------------------------------
// Kernel: output projection + bias. grid (32, 8). 1-MMA, 2 CTAs/SM.
// ---------------------------------------------------------------------------
__global__ __launch_bounds__(256, 2) void gemm_out_mma(
    const float* __restrict__ bias, float* __restrict__ out)
{
    extern __shared__ char smraw[];
    uint32_t sb = (smem_u32(smraw) + 127) & ~127u;
    const size_t row0 = (size_t)blockIdx.x * 128;
    const size_t col0 = (size_t)blockIdx.y * 128;

    float C[4][4][4] = {};
    gemm_core<false, false>(sb, g_atthi, nullptr, row0, g_wphi, nullptr, col0, C);

    const int t = threadIdx.x, w = t >> 5, l = t & 31;
    const int gid = l >> 2, tig = l & 3;
    const int wm = (w & 1) * 64, wn = (w >> 1) * 32;

    #pragma unroll
    for (int i = 0; i < 4; ++i)
        #pragma unroll
        for (int j = 0; j < 4; ++j) {
            size_t col = col0 + wn + 8 * j + 2 * tig;
            size_t r = row0 + wm + 16 * i + gid;
            float2 b2 = *(const float2*)(bias + col);
            *(float2*)(out + r * DM + col) =
                make_float2(C[i][j][0] + b2.x, C[i][j][1] + b2.y);
            *(float2*)(out + (r + 8) * DM + col) =
                make_float2(C[i][j][2] + b2.x, C[i][j][3] + b2.y);
        }
}

// ---------------------------------------------------------------------------
// Flash attention on HMMA (fp16) — unchanged from R13.
// ---------------------------------------------------------------------------
#define ATTN_STAGE 24576
#define ATTN_SMEM (16384 + 4 * ATTN_STAGE + 128)

__device__ __forceinline__ void attn_fill(uint32_t base,
    const hf* khi, const hf* klo, const hf* vthi, int j0)
{
    const int t = threadIdx.x;
    #pragma unroll
    for (int i = 0; i < 2; ++i) {
        int g = i * 256 + t;
        int row = g >> 3, u = g & 7;
        uint32_t s = swz(row, u);
        CP16(base + s,         khi  + (size_t)(j0 + row) * DK + u * 8);
        CP16(base + 8192 + s,  klo  + (size_t)(j0 + row) * DK + u * 8);
        CP16(base + 16384 + s, vthi + (size_t)row * LL + j0 + u * 8);
    }
}

__global__ __launch_bounds__(256, 2) void attn_mma()
{
    extern __shared__ char smraw[];
    const uint32_t sb = (smem_u32(smraw) + 127) & ~127u;
    const uint32_t QLO = sb, ST0 = sb + 16384;

    const int hb = blockIdx.y;
    const int h = hb >> 1, b = hb & 1;
    const int l0 = blockIdx.x * 128;
    const hf* qhi = g_qhi + (size_t)hb * LL * DK;
    const hf* qlo = g_qlo + (size_t)hb * LL * DK;
    const hf* khi = g_khi + (size_t)hb * LL * DK;
    const hf* klo = g_klo + (size_t)hb * LL * DK;
    const hf* vthi = g_vthi + (size_t)hb * DK * LL;

    const int t = threadIdx.x, w = t >> 5, l = t & 31;
    const int gid = l >> 2, tig = l & 3;
    const int mi = l >> 3;

    #pragma unroll
    for (int i = 0; i < 4; ++i) {
        int g = i * 256 + t;
        int row = g >> 3, u = g & 7;
        uint32_t s = swz(row, u);
        *(uint4*)(smraw + (ST0 - sb) + s) =
            *(const uint4*)(qhi + (size_t)(l0 + row) * DK + u * 8);
        *(uint4*)(smraw + (QLO - sb) + s) =
            *(const uint4*)(qlo + (size_t)(l0 + row) * DK + u * 8);
    }
    __syncthreads();

    uint32_t qfh[4][4];
    #pragma unroll
    for (int kt = 0; kt < 4; ++kt) {
        int row = w * 16 + (l & 7) + ((mi & 1) << 3);
        int u = kt * 2 + (mi >> 1);
        ldm4(qfh[kt], ST0 + swz(row, u));
    }
    __syncthreads();

    attn_fill(ST0, khi, klo, vthi, 0);
    CP_COMMIT();
    attn_fill(ST0 + ATTN_STAGE, khi, klo, vthi, 64);
    CP_COMMIT();

    const uint32_t ones2[2] = { 0x3C003C00u, 0x3C003C00u };
    const float L2E = 1.4426950408889634f;

    float o[8][4] = {};
    float osum[4] = {};
    float m0 = -1e30f, m1 = -1e30f;

    for (int jt = 0; jt < 32; ++jt) {
        if (jt + 2 < 32) {
            attn_fill(ST0 + ((jt + 2) & 3) * ATTN_STAGE, khi, klo, vthi,
                      (jt + 2) * 64);
            CP_COMMIT();
            CP_WAIT2();
        } else if (jt + 1 < 32) {
            CP_WAIT1();
        } else {
            CP_WAIT0();
        }
        __syncthreads();
        const uint32_t tb = ST0 + (jt & 3) * ATTN_STAGE;

        float s[8][4] = {};
        #pragma unroll
        for (int kt = 0; kt < 4; ++kt) {
            uint32_t qfl[4];
            {
                int row = w * 16 + (l & 7) + ((mi & 1) << 3);
                int u = kt * 2 + (mi >> 1);
                ldm4(qfl, QLO + swz(row, u));
            }
            uint32_t kh[8][2], kl[8][2];
            #pragma unroll
            for (int jp = 0; jp < 4; ++jp) {
                int row = jp * 16 + ((mi >> 1) << 3) + (l & 7);
                int u = kt * 2 + (mi & 1);
                uint32_t r4[4];
                ldm4(r4, tb + swz(row, u));
                kh[2*jp][0] = r4[0]; kh[2*jp][1] = r4[1];
                kh[2*jp+1][0] = r4[2]; kh[2*jp+1][1] = r4[3];
                ldm4(r4, tb + 8192 + swz(row, u));
                kl[2*jp][0] = r4[0]; kl[2*jp][1] = r4[1];
                kl[2*jp+1][0] = r4[2]; kl[2*jp+1][1] = r4[3];
            }
            #pragma unroll
            for (int n = 0; n < 8; ++n) {
                mma16816(s[n], qfh[kt], kh[n]);
                mma16816(s[n], qfh[kt], kl[n]);
                mma16816(s[n], qfl,     kh[n]);
            }
        }

        float rm0 = -1e30f, rm1 = -1e30f;
        #pragma unroll
        for (int n = 0; n < 8; ++n) {
            rm0 = fmaxf(rm0, fmaxf(s[n][0], s[n][1]));
            rm1 = fmaxf(rm1, fmaxf(s[n][2], s[n][3]));
        }
        rm0 = fmaxf(rm0, __shfl_xor_sync(0xffffffffu, rm0, 1));
        rm0 = fmaxf(rm0, __shfl_xor_sync(0xffffffffu, rm0, 2));
        rm1 = fmaxf(rm1, __shfl_xor_sync(0xffffffffu, rm1, 1));
        rm1 = fmaxf(rm1, __shfl_xor_sync(0xffffffffu, rm1, 2));
        const float mn0 = fmaxf(m0, rm0), mn1 = fmaxf(m1, rm1);
        const float sc0 = __expf(m0 - mn0), sc1 = __expf(m1 - mn1);
        m0 = mn0; m1 = mn1;
        const float mn0L = mn0 * L2E, mn1L = mn1 * L2E;

        uint32_t pp[8][2];
        #pragma unroll
        for (int n = 0; n < 8; ++n) {
            pp[n][0] = ex2_f16x2(pack_hf(fmaf(s[n][0], L2E, -mn0L),
                                         fmaf(s[n][1], L2E, -mn0L)));
            pp[n][1] = ex2_f16x2(pack_hf(fmaf(s[n][2], L2E, -mn1L),
                                         fmaf(s[n][3], L2E, -mn1L)));
        }
        #pragma unroll
        for (int n = 0; n < 8; ++n) {
            o[n][0] *= sc0; o[n][1] *= sc0;
            o[n][2] *= sc1; o[n][3] *= sc1;
        }
        osum[0] *= sc0; osum[1] *= sc0;
        osum[2] *= sc1; osum[3] *= sc1;

        #pragma unroll
        for (int kt = 0; kt < 4; ++kt) {
            uint32_t pah[4] = { pp[2*kt][0], pp[2*kt][1],
                                pp[2*kt+1][0], pp[2*kt+1][1] };
            mma16816(osum, pah, ones2);
            uint32_t vh[8][2];
            #pragma unroll
            for (int jp = 0; jp < 4; ++jp) {
                int row = jp * 16 + ((mi >> 1) << 3) + (l & 7);
                int u = kt * 2 + (mi & 1);
                uint32_t r4[4];
                ldm4(r4, tb + 16384 + swz(row, u));
                vh[2*jp][0] = r4[0]; vh[2*jp][1] = r4[1];
                vh[2*jp+1][0] = r4[2]; vh[2*jp+1][1] = r4[3];
            }
            #pragma unroll
            for (int n = 0; n < 8; ++n)
                mma16816(o[n], pah, vh[n]);
        }
    }

    const float inv0 = 1.0f / osum[0], inv1 = 1.0f / osum[2];
    const size_t r0 = l0 + w * 16 + gid, r1 = r0 + 8;
    #pragma unroll
    for (int n = 0; n < 8; ++n) {
        const int d = 8 * n + 2 * tig;
        __half2 qh2a = *(const __half2*)(qhi + r0 * DK + d);
        __half2 ql2a = *(const __half2*)(qlo + r0 * DK + d);
        __half2 qh2b = *(const __half2*)(qhi + r1 * DK + d);
        __half2 ql2b = *(const __half2*)(qlo + r1 * DK + d);
        float qa0 = __half2float(qh2a.x) + __half2float(ql2a.x);
        float qa1 = __half2float(qh2a.y) + __half2float(ql2a.y);
        float qb0 = __half2float(qh2b.x) + __half2float(ql2b.x);
        float qb1 = __half2float(qh2b.y) + __half2float(ql2b.y);
        float v00 = o[n][0] * inv0 * qa0, v01 = o[n][1] * inv0 * qa1;
        float v10 = o[n][2] * inv1 * qb0, v11 = o[n][3] * inv1 * qb1;

        size_t o0 = ((size_t)b * LL + r0) * DM + h * DK + d;
        size_t o1 = ((size_t)b * LL + r1) * DM + h * DK + d;
        *(uint32_t*)(g_atthi + o0) = pack_hf(v00, v01);
        *(uint32_t*)(g_atthi + o1) = pack_hf(v10, v11);
    }
}

// ---------------------------------------------------------------------------
extern "C" void kernel_launch(void* const* d_in, const int* in_sizes, int n_in,
                              void* d_out, int out_size)
{
    const float* q  = (const float*)d_in[0];
    const float* k  = (const float*)d_in[1];
    const float* v  = (const float*)d_in[2];
    const float* wq = (const float*)d_in[3];
    const float* wk = (const float*)d_in[4];
    const float* wv = (const float*)d_in[5];
    const float* wp = (const float*)d_in[6];
    const float* bp = (const float*)d_in[7];
    float* out = (float*)d_out;

    cudaFuncSetAttribute(gemm_proj_mma,
                         cudaFuncAttributeMaxDynamicSharedMemorySize, GEMM_SMEM);
    cudaFuncSetAttribute(gemm_out_mma,
                         cudaFuncAttributeMaxDynamicSharedMemorySize, GEMM_SMEM);
    cudaFuncSetAttribute(attn_mma,
                         cudaFuncAttributeMaxDynamicSharedMemorySize, ATTN_SMEM);

    const int n4x = MROWS * DM / 4;
    conv_split_kernel<<<dim3((n4x + 255) / 256, 4), 256>>>(q, k, v, wp);
    conv_wt_kernel<<<dim3(NH, 3), 256>>>(wq, wk, wv);

    gemm_proj_mma<<<dim3(MROWS / 128, NH / 2, 3), 256, GEMM_SMEM>>>();

    attn_mma<<<dim3(LL / 128, NH * BB), 256, ATTN_SMEM>>>();

    gemm_out_mma<<<dim3(MROWS / 128, DM / 128), 256, GEMM_SMEM>>>(bp, out);
}